// round 13
// baseline (speedup 1.0000x reference)
#include <cuda_runtime.h>
#include <math.h>

typedef unsigned short u16;
typedef unsigned int   u32;

// ---------------- problem constants ----------------
#define B_SZ 2
#define T_SZ 1024
#define D_SZ 1024
#define H_SZ 16
#define DH_SZ 64
#define FF_SZ 4096
#define L_SZ 2
#define V_SZ 32000
#define M_BLK 32
#define BS_SZ 32
#define TOPK 8
#define KEEP 128
#define EPSF 1e-6f
#define PI_D 3.14159265358979323846

// ---------------- fp32 scratch ----------------
__device__ float d_x  [B_SZ*T_SZ*D_SZ];
__device__ float d_h  [B_SZ*T_SZ*D_SZ];
__device__ float d_qkv[3*B_SZ*T_SZ*D_SZ];            // contiguous q|k|v
__device__ float d_o  [B_SZ*T_SZ*D_SZ];
__device__ float d_sc [(size_t)B_SZ*H_SZ*T_SZ*T_SZ];
__device__ float d_f13[2*B_SZ*T_SZ*FF_SZ];           // contiguous f1|f3
__device__ float d_G  [T_SZ*T_SZ];
__device__ float d_gk [T_SZ];
__device__ float d_rho[B_SZ*T_SZ];
__device__ int   d_sel[B_SZ*M_BLK];

// ---------------- bf16 hi/lo planes ----------------
__device__ u16 d_xh  [B_SZ*T_SZ*D_SZ],   d_xl  [B_SZ*T_SZ*D_SZ];
__device__ u16 d_Gh  [T_SZ*T_SZ],        d_Gl  [T_SZ*T_SZ];
__device__ u16 d_hh  [B_SZ*T_SZ*D_SZ],   d_hl  [B_SZ*T_SZ*D_SZ];
__device__ u16 d_qkvh[3*B_SZ*T_SZ*D_SZ], d_qkvl[3*B_SZ*T_SZ*D_SZ];
__device__ u16 d_sch [(size_t)B_SZ*H_SZ*T_SZ*T_SZ], d_scl[(size_t)B_SZ*H_SZ*T_SZ*T_SZ];
__device__ u16 d_oh  [B_SZ*T_SZ*D_SZ],   d_ol  [B_SZ*T_SZ*D_SZ];
__device__ u16 d_f1h [B_SZ*T_SZ*FF_SZ],  d_f1l [B_SZ*T_SZ*FF_SZ];
// weights (natural [K][N] layout planes)
__device__ u16 d_wqkvh[L_SZ*3*D_SZ*D_SZ], d_wqkvl[L_SZ*3*D_SZ*D_SZ];
__device__ u16 d_woh [L_SZ*D_SZ*D_SZ],   d_wol [L_SZ*D_SZ*D_SZ];
__device__ u16 d_w13h[L_SZ*2*D_SZ*FF_SZ], d_w13l[L_SZ*2*D_SZ*FF_SZ];
__device__ u16 d_w2h [L_SZ*FF_SZ*D_SZ],  d_w2l [L_SZ*FF_SZ*D_SZ];
__device__ u16 d_lmh [(size_t)D_SZ*V_SZ], d_lml [(size_t)D_SZ*V_SZ];

// ---------------- split helpers ----------------
__device__ __forceinline__ void split2(float v0, float v1, u32 &hi, u32 &lo)
{
    asm("cvt.rn.bf16x2.f32 %0, %1, %2;" : "=r"(hi) : "f"(v1), "f"(v0));
    float h0 = __int_as_float(hi << 16);
    float h1 = __int_as_float(hi & 0xffff0000u);
    asm("cvt.rn.bf16x2.f32 %0, %1, %2;" : "=r"(lo) : "f"(v1 - h1), "f"(v0 - h0));
}

__global__ __launch_bounds__(256) void split_kernel(const float* __restrict__ in,
                                                    uint2* __restrict__ hi, uint2* __restrict__ lo,
                                                    long n4)
{
    long idx = (long)blockIdx.x * blockDim.x + threadIdx.x;
    if (idx >= n4) return;
    float4 v = reinterpret_cast<const float4*>(in)[idx];
    u32 h0, l0, h1, l1;
    split2(v.x, v.y, h0, l0);
    split2(v.z, v.w, h1, l1);
    hi[idx] = make_uint2(h0, h1);
    lo[idx] = make_uint2(l0, l1);
}

#define MMA_BF16(ACC, A, B0, B1)                                                 \
    asm volatile(                                                                \
        "mma.sync.aligned.m16n8k16.row.col.f32.bf16.bf16.f32 "                   \
        "{%0,%1,%2,%3}, {%4,%5,%6,%7}, {%8,%9}, {%0,%1,%2,%3};"                  \
        : "+f"(ACC[0]), "+f"(ACC[1]), "+f"(ACC[2]), "+f"(ACC[3])                 \
        : "r"(A[0]), "r"(A[1]), "r"(A[2]), "r"(A[3]), "r"(B0), "r"(B1))

#define LDSM4(R, ADDR)                                                           \
    asm volatile("ldmatrix.sync.aligned.m8n8.x4.shared.b16 {%0,%1,%2,%3},[%4];"  \
        : "=r"(R[0]), "=r"(R[1]), "=r"(R[2]), "=r"(R[3]) : "r"(ADDR))

#define LDSM4T(R0, R1, R2, R3, ADDR)                                             \
    asm volatile("ldmatrix.sync.aligned.m8n8.x4.trans.shared.b16 {%0,%1,%2,%3},[%4];" \
        : "=r"(R0), "=r"(R1), "=r"(R2), "=r"(R3) : "r"(ADDR))

// =====================================================================
// bf16 hi/lo 3-term GEMM, NSTG-stage cp.async pipeline, sparse modes.
// smode 0: dense. smode 1: scores (skip dead tiles). smode 2: attn@V.
// Optional Chp/Clp: epilogue also emits bf16 hi/lo planes (beta=0 only).
// BNK=true: B stored row-major [N][K]. 256 threads, BM=128, BK=32.
// =====================================================================
#define LDA_S 40   // u16 stride (80B)

template<int BN, int WM, int WN, int NSTG, bool BNK>
__global__ __launch_bounds__(256, 2)
void bf16_gemm_kernel(const u16* __restrict__ Ahi, const u16* __restrict__ Alo,
                      const u16* __restrict__ Bhi, const u16* __restrict__ Blo,
                      float* __restrict__ Cg,
                      int K, int lda, int ldb, int ldc,
                      long sAb, long sBb, long sCb, long sAh, long sBh, long sCh,
                      int Hdim, int beta,
                      const int* __restrict__ selp, int smode,
                      u32* __restrict__ Chp, u32* __restrict__ Clp)
{
    constexpr int BM = 128, BK = 32;
    constexpr int AM = BM / WM / 16;
    constexpr int AN = BN / WN / 8;
    constexpr int LDB_S = BNK ? LDA_S : (BN + 8);
    constexpr int A_PL  = BM * LDA_S;
    constexpr int B_PL  = BNK ? (BN * LDA_S) : (BK * LDB_S);
    constexpr int STAGE = 2 * A_PL + 2 * B_PL;

    extern __shared__ u16 smu[];
    __shared__ int klist[129];
    __shared__ int kcnt;

    int z = blockIdx.z, zb = z / Hdim, zh = z % Hdim;
    const int tid = threadIdx.x, lane = tid & 31, w = tid >> 5;
    const int row0 = blockIdx.y * BM, col0 = blockIdx.x * BN;

    if (smode == 1) {
        int qbmin = row0 >> 5, qbmax = qbmin + 3;
        bool need = false;
#pragma unroll
        for (int i = 0; i < BN / 32; i++) {
            int kb = (col0 >> 5) + i;
            if (kb <= qbmax && (selp[zb * M_BLK + kb] || kb >= qbmin)) need = true;
        }
        if (!need) return;
    }
    if (tid == 0) {
        int c = 0;
        if (smode == 2) {
            int qbmin = row0 >> 5, qbmax = qbmin + 3;
            for (int kb = 0; kb < K / 32; kb++)
                if (kb <= qbmax && (selp[zb * M_BLK + kb] || kb >= qbmin))
                    klist[c++] = kb * 32;
        } else {
            for (int t = 0; t < K / BK; t++) klist[c++] = t * BK;
        }
        kcnt = c;
    }
    __syncthreads();
    const int ntiles = kcnt;

    const u16* Ah = Ahi + zb * sAb + zh * sAh;
    const u16* Al = Alo + zb * sAb + zh * sAh;
    const u16* Bh = Bhi + zb * sBb + zh * sBh;
    const u16* Bl = Blo + zb * sBb + zh * sBh;
    float*     C  = Cg  + zb * sCb + zh * sCh;
    u32* Ch = Chp ? Chp + (zb * sCb + zh * sCh) / 2 : (u32*)0;
    u32* Cl = Clp ? Clp + (zb * sCb + zh * sCh) / 2 : (u32*)0;

    const int wm = w % WM, wn = w / WM;
    const int mW = wm * (BM / WM), nW = wn * (BN / WN);

    float acc[AM][AN][4];
#pragma unroll
    for (int i = 0; i < AM; i++)
#pragma unroll
        for (int j = 0; j < AN; j++)
#pragma unroll
            for (int r = 0; r < 4; r++) acc[i][j][r] = 0.f;

    auto cpa = [&](u16* dst, const u16* src) {
        u32 d = (u32)__cvta_generic_to_shared(dst);
        asm volatile("cp.async.cg.shared.global [%0],[%1],16;\n" :: "r"(d), "l"(src));
    };
    auto load_tile = [&](int s, int kt) {
        u16* base = smu + s * STAGE;
#pragma unroll
        for (int i = 0; i < 2; i++) {
            int ch = tid + i * 256;
            int r = ch >> 2, c = ch & 3;
            size_t go = (size_t)(row0 + r) * lda + kt + c * 8;
            cpa(base + r * LDA_S + c * 8,        Ah + go);
            cpa(base + A_PL + r * LDA_S + c * 8, Al + go);
        }
        u16* bb = base + 2 * A_PL;
        if (BNK) {
            constexpr int BIT = (BN * 4) / 256;
#pragma unroll
            for (int i = 0; i < BIT; i++) {
                int ch = tid + i * 256;
                int r = ch >> 2, c = ch & 3;
                size_t go = (size_t)(col0 + r) * ldb + kt + c * 8;
                cpa(bb + r * LDA_S + c * 8,        Bh + go);
                cpa(bb + B_PL + r * LDA_S + c * 8, Bl + go);
            }
        } else {
            constexpr int CPR = BN / 8;
            constexpr int BIT = (BK * CPR) / 256;
#pragma unroll
            for (int i = 0; i < BIT; i++) {
                int ch = tid + i * 256;
                int r = ch / CPR, c = ch % CPR;
                size_t go = (size_t)(kt + r) * ldb + col0 + c * 8;
                cpa(bb + r * LDB_S + c * 8,        Bh + go);
                cpa(bb + B_PL + r * LDB_S + c * 8, Bl + go);
            }
        }
    };

    // NSTG-stage pipeline: preload NSTG-1 tiles.
    load_tile(0, klist[0]);
    asm volatile("cp.async.commit_group;\n" ::: "memory");
    if (NSTG >= 3 && ntiles > 1) {
        load_tile(1, klist[1]);
        asm volatile("cp.async.commit_group;\n" ::: "memory");
    }

    for (int t = 0; t < ntiles; t++) {
        int s = t % NSTG;
        if (NSTG == 2) {
            // load next BEFORE waiting (classic double buffer)
            if (t + 1 < ntiles) {
                load_tile((t + 1) % NSTG, klist[t + 1]);
                asm volatile("cp.async.commit_group;\n" ::: "memory");
                asm volatile("cp.async.wait_group 1;\n" ::: "memory");
            } else {
                asm volatile("cp.async.wait_group 0;\n" ::: "memory");
            }
            __syncthreads();
        } else {
            if (t + 1 < ntiles) {
                asm volatile("cp.async.wait_group 1;\n" ::: "memory");
            } else {
                asm volatile("cp.async.wait_group 0;\n" ::: "memory");
            }
            __syncthreads();
            if (t + 2 < ntiles) {
                load_tile((t + 2) % NSTG, klist[t + 2]);
                asm volatile("cp.async.commit_group;\n" ::: "memory");
            }
        }

        const u16* sa = smu + s * STAGE;
        const u16* sb = sa + 2 * A_PL;
#pragma unroll
        for (int ks = 0; ks < 2; ks++) {
            u32 ah[AM][4], al[AM][4], bh[AN][2], bl[AN][2];
            int arow = ((lane >> 3) & 1) * 8 + (lane & 7);
            int acol = ks * 16 + (lane >> 4) * 8;
#pragma unroll
            for (int am = 0; am < AM; am++) {
                const u16* p = sa + (mW + am * 16 + arow) * LDA_S + acol;
                u32 addr = (u32)__cvta_generic_to_shared(p);
                LDSM4(ah[am], addr);
                LDSM4(al[am], addr + A_PL * 2);
            }
            if (BNK) {
                int brow = ((lane >> 4) & 1) * 8 + (lane & 7);
                int bcol = ks * 16 + ((lane >> 3) & 1) * 8;
#pragma unroll
                for (int a2 = 0; a2 < AN / 2; a2++) {
                    const u16* p = sb + (nW + a2 * 16 + brow) * LDA_S + bcol;
                    u32 addr = (u32)__cvta_generic_to_shared(p);
                    asm volatile("ldmatrix.sync.aligned.m8n8.x4.shared.b16 {%0,%1,%2,%3},[%4];"
                        : "=r"(bh[2*a2][0]), "=r"(bh[2*a2][1]),
                          "=r"(bh[2*a2+1][0]), "=r"(bh[2*a2+1][1]) : "r"(addr));
                    asm volatile("ldmatrix.sync.aligned.m8n8.x4.shared.b16 {%0,%1,%2,%3},[%4];"
                        : "=r"(bl[2*a2][0]), "=r"(bl[2*a2][1]),
                          "=r"(bl[2*a2+1][0]), "=r"(bl[2*a2+1][1]) : "r"(addr + B_PL * 2));
                }
            } else {
                int brow = ks * 16 + ((lane >> 3) & 1) * 8 + (lane & 7);
                int bcol = (lane >> 4) * 8;
#pragma unroll
                for (int a2 = 0; a2 < AN / 2; a2++) {
                    const u16* p = sb + brow * LDB_S + nW + a2 * 16 + bcol;
                    u32 addr = (u32)__cvta_generic_to_shared(p);
                    LDSM4T(bh[2*a2][0], bh[2*a2][1], bh[2*a2+1][0], bh[2*a2+1][1], addr);
                    LDSM4T(bl[2*a2][0], bl[2*a2][1], bl[2*a2+1][0], bl[2*a2+1][1],
                           addr + B_PL * 2);
                }
            }
#pragma unroll
            for (int am = 0; am < AM; am++)
#pragma unroll
                for (int an = 0; an < AN; an++) {
                    MMA_BF16(acc[am][an], ah[am], bh[an][0], bh[an][1]);
                    MMA_BF16(acc[am][an], ah[am], bl[an][0], bl[an][1]);
                    MMA_BF16(acc[am][an], al[am], bh[an][0], bh[an][1]);
                }
        }
        __syncthreads();
    }

#pragma unroll
    for (int am = 0; am < AM; am++)
#pragma unroll
        for (int an = 0; an < AN; an++) {
            int r = row0 + mW + am * 16 + (lane >> 2);
            int c = col0 + nW + an * 8 + (lane & 3) * 2;
            size_t i0 = (size_t)r * ldc + c;
            size_t i1 = (size_t)(r + 8) * ldc + c;
            float2 v0 = make_float2(acc[am][an][0], acc[am][an][1]);
            float2 v1 = make_float2(acc[am][an][2], acc[am][an][3]);
            if (beta) {
                float2 p0 = *reinterpret_cast<const float2*>(C + i0);
                float2 p1 = *reinterpret_cast<const float2*>(C + i1);
                v0.x += p0.x; v0.y += p0.y; v1.x += p1.x; v1.y += p1.y;
            }
            *reinterpret_cast<float2*>(C + i0) = v0;
            *reinterpret_cast<float2*>(C + i1) = v1;
            if (Ch) {
                u32 hh_, ll_;
                split2(v0.x, v0.y, hh_, ll_);
                Ch[i0 >> 1] = hh_; Cl[i0 >> 1] = ll_;
                split2(v1.x, v1.y, hh_, ll_);
                Ch[i1 >> 1] = hh_; Cl[i1 >> 1] = ll_;
            }
        }
}

// ---------------- elementwise kernels ----------------
__global__ void embed_split_kernel(const int* __restrict__ ids, const float* __restrict__ emb,
                                   float* __restrict__ x, u32* __restrict__ xh, u32* __restrict__ xl)
{
    int idx = blockIdx.x * blockDim.x + threadIdx.x;   // B*T*D/2
    int d2 = idx & 511;
    int bt = idx >> 9;
    float2 v = *reinterpret_cast<const float2*>(emb + (size_t)ids[bt] * D_SZ + d2 * 2);
    *reinterpret_cast<float2*>(x + (size_t)bt * D_SZ + d2 * 2) = v;
    u32 h, l;
    split2(v.x, v.y, h, l);
    xh[idx] = h; xl[idx] = l;
}

__global__ void dirichlet_kernel(float* __restrict__ g)
{
    int d = blockIdx.x * blockDim.x + threadIdx.x;
    if (d >= T_SZ) return;
    double s = 0.0;
    for (int k = 1; k < KEEP; k++)
        s += cos(2.0 * PI_D * (double)k * (double)d / (double)T_SZ);
    g[d] = (float)((1.0 + 2.0 * s) / (double)T_SZ);
}

__global__ void buildG_kernel(const float* __restrict__ g, float* __restrict__ G)
{
    int i = blockIdx.x * blockDim.x + threadIdx.x;
    int t = i >> 10, s = i & (T_SZ - 1);
    G[i] = g[(t - s) & (T_SZ - 1)];
}

__global__ __launch_bounds__(256) void rho_kernel(const float* __restrict__ hlp,
                                                  const float* __restrict__ x,
                                                  float* __restrict__ rho)
{
    size_t row = (size_t)blockIdx.x * D_SZ;
    int tid = threadIdx.x;
    float s1 = 0.f, s2 = 0.f;
#pragma unroll
    for (int i = 0; i < 4; i++) {
        float a = hlp[row + tid + i * 256];
        float b = x  [row + tid + i * 256];
        s1 += a * a; s2 += b * b;
    }
    for (int o = 16; o > 0; o >>= 1) {
        s1 += __shfl_xor_sync(0xffffffffu, s1, o);
        s2 += __shfl_xor_sync(0xffffffffu, s2, o);
    }
    __shared__ float r1[8], r2[8];
    if ((tid & 31) == 0) { r1[tid >> 5] = s1; r2[tid >> 5] = s2; }
    __syncthreads();
    if (tid == 0) {
        float t1 = 0.f, t2 = 0.f;
        for (int i = 0; i < 8; i++) { t1 += r1[i]; t2 += r2[i]; }
        rho[blockIdx.x] = t1 / (t2 + EPSF);
    }
}

__global__ void select_blocks(const float* __restrict__ rho, int* __restrict__ sel)
{
    __shared__ float bq[B_SZ][M_BLK];
    int tid = threadIdx.x;
    if (tid < B_SZ * M_BLK) {
        int b = tid >> 5, m = tid & 31;
        float s = 0.f;
        for (int i = 0; i < BS_SZ; i++) s += rho[b * T_SZ + m * BS_SZ + i];
        bq[b][m] = s * (1.f / BS_SZ);
        sel[tid] = 0;
    }
    __syncthreads();
    if (tid < B_SZ) {
        int b = tid;
        bool picked[M_BLK];
        for (int m = 0; m < M_BLK; m++) picked[m] = false;
        for (int it = 0; it < TOPK; it++) {
            int best = -1; float bv = -3.4e38f;
            for (int m = 0; m < M_BLK; m++)
                if (!picked[m] && bq[b][m] > bv) { bv = bq[b][m]; best = m; }
            picked[best] = true;
            sel[b * M_BLK + best] = 1;
        }
    }
}

__global__ __launch_bounds__(256) void rmsnorm_split_kernel(
    const float* __restrict__ x, const float* __restrict__ w,
    u32* __restrict__ yh, u32* __restrict__ yl)
{
    size_t row = (size_t)blockIdx.x * D_SZ;
    int tid = threadIdx.x;
    float4 v = reinterpret_cast<const float4*>(x + row)[tid];
    float s = v.x * v.x + v.y * v.y + v.z * v.z + v.w * v.w;
    for (int o = 16; o > 0; o >>= 1) s += __shfl_xor_sync(0xffffffffu, s, o);
    __shared__ float red[8];
    if ((tid & 31) == 0) red[tid >> 5] = s;
    __syncthreads();
    float tot = 0.f;
    for (int i = 0; i < 8; i++) tot += red[i];
    float r = rsqrtf(tot * (1.f / D_SZ) + EPSF);
    float4 wv = reinterpret_cast<const float4*>(w)[tid];
    u32 h0, l0, h1, l1;
    split2(v.x * r * wv.x, v.y * r * wv.y, h0, l0);
    split2(v.z * r * wv.z, v.w * r * wv.w, h1, l1);
    size_t c = row / 2 + tid * 2;
    yh[c] = h0; yh[c + 1] = h1;
    yl[c] = l0; yl[c + 1] = l1;
}

__global__ void rope_split_kernel(const float* __restrict__ qkv,
                                  u32* __restrict__ qkvh, u32* __restrict__ qkvl)
{
    const int QK = B_SZ * T_SZ * D_SZ;
    int idx = blockIdx.x * blockDim.x + threadIdx.x;   // B*T*H*16
    int j2 = idx & 15;
    int h  = (idx >> 4) & (H_SZ - 1);
    int t  = (idx >> 8) & (T_SZ - 1);
    int b  = idx >> 18;
    int e0 = 2 * j2;
    float inv0 = (float)(1.0 / pow(10000.0, (double)(2 * e0)     / (double)DH_SZ));
    float inv1 = (float)(1.0 / pow(10000.0, (double)(2 * (e0+1)) / (double)DH_SZ));
    float c0 = cosf(t * inv0), s0 = sinf(t * inv0);
    float c1 = cosf(t * inv1), s1 = sinf(t * inv1);
    size_t base = ((size_t)(b * T_SZ + t)) * D_SZ + h * DH_SZ + e0;
    float2 qa = *reinterpret_cast<const float2*>(qkv + base);
    float2 qb = *reinterpret_cast<const float2*>(qkv + base + 32);
    float2 ka = *reinterpret_cast<const float2*>(qkv + QK + base);
    float2 kb = *reinterpret_cast<const float2*>(qkv + QK + base + 32);
    float q0 = qa.x * c0 - qb.x * s0, q1 = qa.y * c1 - qb.y * s1;
    float q2 = qb.x * c0 + qa.x * s0, q3 = qb.y * c1 + qa.y * s1;
    float k0 = ka.x * c0 - kb.x * s0, k1 = ka.y * c1 - kb.y * s1;
    float k2 = kb.x * c0 + ka.x * s0, k3 = kb.y * c1 + ka.y * s1;
    size_t p0 = base >> 1, p1 = (base + 32) >> 1;
    const size_t QK2 = QK / 2;
    u32 hh_, ll_;
    split2(q0, q1, hh_, ll_); qkvh[p0] = hh_;       qkvl[p0] = ll_;
    split2(q2, q3, hh_, ll_); qkvh[p1] = hh_;       qkvl[p1] = ll_;
    split2(k0, k1, hh_, ll_); qkvh[QK2 + p0] = hh_; qkvl[QK2 + p0] = ll_;
    split2(k2, k3, hh_, ll_); qkvh[QK2 + p1] = hh_; qkvl[QK2 + p1] = ll_;
}

__global__ __launch_bounds__(256) void masked_softmax_split_kernel(
    const float* __restrict__ s, const int* __restrict__ sel,
    u32* __restrict__ ph, u32* __restrict__ pl)
{
    int gid = blockIdx.x;
    int tq = gid & (T_SZ - 1);
    int b  = gid / (H_SZ * T_SZ);
    size_t row = (size_t)gid * T_SZ;
    int tid = threadIdx.x;
    const float scale = 0.125f;
    int qblk  = tq >> 5;
    int qbmin = (tq >> 7) << 2;
    int qbmax = qbmin + 3;

    float v[4];
    bool wlive[2];
    float mx = -3.4e38f;
#pragma unroll
    for (int i = 0; i < 2; i++) {
        int p  = tid + i * 256;
        int kb = p >> 4;
        bool blive = (kb <= qblk) && (sel[b * M_BLK + kb] || kb == qblk);
        wlive[i]   = (kb <= qbmax) && (sel[b * M_BLK + kb] || kb >= qbmin);
        float2 vv = make_float2(-1e9f, -1e9f);
        if (blive) vv = *reinterpret_cast<const float2*>(s + row + 2 * p);
        int e0 = 2 * p;
        v[2*i]   = (blive && e0     <= tq) ? vv.x * scale : -1e9f;
        v[2*i+1] = (blive && e0 + 1 <= tq) ? vv.y * scale : -1e9f;
        mx = fmaxf(mx, fmaxf(v[2*i], v[2*i+1]));
    }
    for (int o = 16; o > 0; o >>= 1) mx = fmaxf(mx, __shfl_xor_sync(0xffffffffu, mx, o));
    __shared__ float red[8];
    if ((tid & 31) == 0) red[tid >> 5] = mx;
    __syncthreads();
    float m = red[0];
    for (int i = 1; i < 8; i++) m = fmaxf(m, red[i]);
    __syncthreads();
    float sum = 0.f;
#pragma unroll
    for (int i = 0; i < 4; i++) { v[i] = expf(v[i] - m); sum += v[i]; }
    for (int o = 16; o > 0; o >>= 1) sum += __shfl_xor_sync(0xffffffffu, sum, o);
    if ((tid & 31) == 0) red[tid >> 5] = sum;
    __syncthreads();
    float tot = 0.f;
    for (int i = 0; i < 8; i++) tot += red[i];
    float inv = 1.f / tot;
    size_t prow = row >> 1;
#pragma unroll
    for (int i = 0; i < 2; i++) {
        if (!wlive[i]) continue;
        int p = tid + i * 256;
        u32 hh_, ll_;
        split2(v[2*i] * inv, v[2*i+1] * inv, hh_, ll_);
        ph[prow + p] = hh_; pl[prow + p] = ll_;
    }
}

__global__ __launch_bounds__(256) void silu_split_kernel(const float* __restrict__ f13,
                                                         u32* __restrict__ gh, u32* __restrict__ gl,
                                                         long n2)
{
    long idx = (long)blockIdx.x * blockDim.x + threadIdx.x;
    if (idx >= n2) return;
    const long F3OFF = (long)B_SZ * T_SZ * FF_SZ / 2;
    float2 a = reinterpret_cast<const float2*>(f13)[idx];
    float2 g = reinterpret_cast<const float2*>(f13)[F3OFF + idx];
    float y0 = a.x / (1.f + expf(-a.x)) * g.x;
    float y1 = a.y / (1.f + expf(-a.y)) * g.y;
    u32 h, l;
    split2(y0, y1, h, l);
    gh[idx] = h; gl[idx] = l;
}

// ---------------- host launchers ----------------
static const int SMEM_KN64  = 3 * (2*128*LDA_S + 2*32*(64+8))  * 2;
static const int SMEM_KN128 = 2 * (2*128*LDA_S + 2*32*(128+8)) * 2;
static const int SMEM_NK64  = 3 * (2*128*LDA_S + 2*64*LDA_S)   * 2;

static void gemm_kn(const u16* Ah, const u16* Al, const u16* Bh, const u16* Bl, float* C,
                    int M, int N, int K, int lda, int ldb, int ldc,
                    long sAb, long sBb, long sCb, long sAh, long sBh, long sCh,
                    int Hdim, int nb, int beta,
                    const int* sel = 0, int smode = 0, u16* Ch = 0, u16* Cl = 0)
{
    long ctas128 = (long)(N / 128) * (M / 128) * nb;
    if (smode == 0 && N % 128 == 0 && ctas128 >= 256) {
        dim3 grid(N / 128, M / 128, nb);
        bf16_gemm_kernel<128, 2, 4, 2, false><<<grid, 256, SMEM_KN128>>>(
            Ah, Al, Bh, Bl, C, K, lda, ldb, ldc, sAb, sBb, sCb, sAh, sBh, sCh, Hdim, beta,
            sel, smode, (u32*)Ch, (u32*)Cl);
    } else {
        dim3 grid(N / 64, M / 128, nb);
        bf16_gemm_kernel<64, 4, 2, 3, false><<<grid, 256, SMEM_KN64>>>(
            Ah, Al, Bh, Bl, C, K, lda, ldb, ldc, sAb, sBb, sCb, sAh, sBh, sCh, Hdim, beta,
            sel, smode, (u32*)Ch, (u32*)Cl);
    }
}

static void gemm_nk(const u16* Ah, const u16* Al, const u16* Bh, const u16* Bl, float* C,
                    int M, int N, int K, int lda, int ldb, int ldc,
                    long sAb, long sBb, long sCb, long sAh, long sBh, long sCh,
                    int Hdim, int nb, int beta, const int* sel, int smode)
{
    dim3 grid(N / 64, M / 128, nb);
    bf16_gemm_kernel<64, 4, 2, 3, true><<<grid, 256, SMEM_NK64>>>(
        Ah, Al, Bh, Bl, C, K, lda, ldb, ldc, sAb, sBb, sCb, sAh, sBh, sCh, Hdim, beta,
        sel, smode, (u32*)0, (u32*)0);
}

static void split(const float* in, u16* hi, u16* lo, long n)
{
    long n4 = n / 4;
    split_kernel<<<(unsigned)((n4 + 255) / 256), 256>>>(in, (uint2*)hi, (uint2*)lo, n4);
}

extern "C" void kernel_launch(void* const* d_in, const int* in_sizes, int n_in,
                              void* d_out, int out_size)
{
    const int*   ids        = (const int*)  d_in[0];
    const float* emb        = (const float*)d_in[1];
    const float* wq         = (const float*)d_in[2];
    const float* wk         = (const float*)d_in[3];
    const float* wv         = (const float*)d_in[4];
    const float* wo         = (const float*)d_in[5];
    const float* w1         = (const float*)d_in[6];
    const float* w2         = (const float*)d_in[7];
    const float* w3         = (const float*)d_in[8];
    const float* attn_norm  = (const float*)d_in[9];
    const float* ffn_norm   = (const float*)d_in[10];
    const float* final_norm = (const float*)d_in[11];
    const float* lm_head    = (const float*)d_in[12];
    float* out = (float*)d_out;

    static bool attrs_set = false;
    if (!attrs_set) {
        cudaFuncSetAttribute((const void*)bf16_gemm_kernel<64, 4, 2, 3, false>,
                             cudaFuncAttributeMaxDynamicSharedMemorySize, SMEM_KN64);
        cudaFuncSetAttribute((const void*)bf16_gemm_kernel<128, 2, 4, 2, false>,
                             cudaFuncAttributeMaxDynamicSharedMemorySize, SMEM_KN128);
        cudaFuncSetAttribute((const void*)bf16_gemm_kernel<64, 4, 2, 3, true>,
                             cudaFuncAttributeMaxDynamicSharedMemorySize, SMEM_NK64);
        attrs_set = true;
    }

    float *x, *h, *qkv, *o, *sc, *f13, *G, *gk, *rho;
    int* sel;
    cudaGetSymbolAddress((void**)&x,   d_x);
    cudaGetSymbolAddress((void**)&h,   d_h);
    cudaGetSymbolAddress((void**)&qkv, d_qkv);
    cudaGetSymbolAddress((void**)&o,   d_o);
    cudaGetSymbolAddress((void**)&sc,  d_sc);
    cudaGetSymbolAddress((void**)&f13, d_f13);
    cudaGetSymbolAddress((void**)&G,   d_G);
    cudaGetSymbolAddress((void**)&gk,  d_gk);
    cudaGetSymbolAddress((void**)&rho, d_rho);
    cudaGetSymbolAddress((void**)&sel, d_sel);

    u16 *xh,*xl,*Gh,*Gl,*hh,*hl,*qkvh,*qkvl,*sch,*scl,*oh,*ol,*f1h,*f1l;
    u16 *wqkvh,*wqkvl,*woh,*wol,*w13h,*w13l,*w2h,*w2l,*lmh,*lml;
    cudaGetSymbolAddress((void**)&xh, d_xh);     cudaGetSymbolAddress((void**)&xl, d_xl);
    cudaGetSymbolAddress((void**)&Gh, d_Gh);     cudaGetSymbolAddress((void**)&Gl, d_Gl);
    cudaGetSymbolAddress((void**)&hh, d_hh);     cudaGetSymbolAddress((void**)&hl, d_hl);
    cudaGetSymbolAddress((void**)&qkvh, d_qkvh); cudaGetSymbolAddress((void**)&qkvl, d_qkvl);
    cudaGetSymbolAddress((void**)&sch, d_sch);   cudaGetSymbolAddress((void**)&scl, d_scl);
    cudaGetSymbolAddress((void**)&oh, d_oh);     cudaGetSymbolAddress((void**)&ol, d_ol);
    cudaGetSymbolAddress((void**)&f1h, d_f1h);   cudaGetSymbolAddress((void**)&f1l, d_f1l);
    cudaGetSymbolAddress((void**)&wqkvh, d_wqkvh); cudaGetSymbolAddress((void**)&wqkvl, d_wqkvl);
    cudaGetSymbolAddress((void**)&woh, d_woh);   cudaGetSymbolAddress((void**)&wol, d_wol);
    cudaGetSymbolAddress((void**)&w13h, d_w13h); cudaGetSymbolAddress((void**)&w13l, d_w13l);
    cudaGetSymbolAddress((void**)&w2h, d_w2h);   cudaGetSymbolAddress((void**)&w2l, d_w2l);
    cudaGetSymbolAddress((void**)&lmh, d_lmh);   cudaGetSymbolAddress((void**)&lml, d_lml);

    const int  BT = B_SZ * T_SZ;
    const long DD = (long)D_SZ * D_SZ;
    const long DF = (long)D_SZ * FF_SZ;
    const long QK = (long)BT * D_SZ;

    // weight splits into concatenated plane buffers
    for (int l = 0; l < L_SZ; l++) {
        split(wq + l * DD, wqkvh + (3 * l + 0) * DD, wqkvl + (3 * l + 0) * DD, DD);
        split(wk + l * DD, wqkvh + (3 * l + 1) * DD, wqkvl + (3 * l + 1) * DD, DD);
        split(wv + l * DD, wqkvh + (3 * l + 2) * DD, wqkvl + (3 * l + 2) * DD, DD);
        split(w1 + l * DF, w13h + (2 * l + 0) * DF, w13l + (2 * l + 0) * DF, DF);
        split(w3 + l * DF, w13h + (2 * l + 1) * DF, w13l + (2 * l + 1) * DF, DF);
    }
    split(wo, woh, wol, (long)L_SZ * DD);
    split(w2, w2h, w2l, (long)L_SZ * DF);
    split(lm_head, lmh, lml, (long)D_SZ * V_SZ);

    // 1) embedding (+split)
    embed_split_kernel<<<(B_SZ * T_SZ * D_SZ / 2) / 256, 256>>>(
        ids, emb, x, (u32*)xh, (u32*)xl);

    // 2) low-pass quality -> block selection
    dirichlet_kernel<<<T_SZ / 256, 256>>>(gk);
    buildG_kernel<<<(T_SZ * T_SZ) / 256, 256>>>(gk, G);
    split(G, Gh, Gl, (long)T_SZ * T_SZ);
    gemm_kn(Gh, Gl, xh, xl, h, T_SZ, D_SZ, T_SZ, T_SZ, D_SZ, D_SZ,
            0, (long)T_SZ * D_SZ, (long)T_SZ * D_SZ, 0, 0, 0, 1, B_SZ, 0);
    rho_kernel<<<BT, 256>>>(h, x, rho);
    select_blocks<<<1, 64>>>(rho, sel);

    // 3) transformer layers
    for (int l = 0; l < L_SZ; l++) {
        rmsnorm_split_kernel<<<BT, 256>>>(x, attn_norm + (size_t)l * D_SZ, (u32*)hh, (u32*)hl);

        // fused QKV (z in {0,1,2}), wide-tile path
        gemm_kn(hh, hl, wqkvh + 3 * l * DD, wqkvl + 3 * l * DD, qkv,
                BT, D_SZ, D_SZ, D_SZ, D_SZ, D_SZ,
                0, 0, 0, 0, DD, QK, 3, 3, 0, 0, 0,
                (u16*)qkvh, (u16*)qkvl);

        rope_split_kernel<<<(B_SZ * T_SZ * H_SZ * 16) / 256, 256>>>(
            qkv, (u32*)qkvh, (u32*)qkvl);

        gemm_nk(qkvh, qkvl, qkvh + QK, qkvl + QK, sc, T_SZ, T_SZ, DH_SZ,
                D_SZ, D_SZ, T_SZ,
                (long)T_SZ * D_SZ, (long)T_SZ * D_SZ, (long)H_SZ * T_SZ * T_SZ,
                DH_SZ, DH_SZ, (long)T_SZ * T_SZ, H_SZ, B_SZ * H_SZ, 0, sel, 1);

        masked_softmax_split_kernel<<<B_SZ * H_SZ * T_SZ, 256>>>(
            sc, sel, (u32*)sch, (u32*)scl);

        gemm_kn(sch, scl, qkvh + 2 * QK, qkvl + 2 * QK, o, T_SZ, DH_SZ, T_SZ,
                T_SZ, D_SZ, D_SZ,
                (long)H_SZ * T_SZ * T_SZ, (long)T_SZ * D_SZ, (long)T_SZ * D_SZ,
                (long)T_SZ * T_SZ, DH_SZ, DH_SZ, H_SZ, B_SZ * H_SZ, 0, sel, 2, oh, ol);

        gemm_kn(oh, ol, woh + l * DD, wol + l * DD, x, BT, D_SZ, D_SZ, D_SZ, D_SZ, D_SZ,
                0, 0, 0, 0, 0, 0, 1, 1, 1);

        // FFN: fused w1/w3 (z in {0,1}), wide-tile path
        rmsnorm_split_kernel<<<BT, 256>>>(x, ffn_norm + (size_t)l * D_SZ, (u32*)hh, (u32*)hl);
        gemm_kn(hh, hl, w13h + 2 * l * DF, w13l + 2 * l * DF, f13,
                BT, FF_SZ, D_SZ, D_SZ, FF_SZ, FF_SZ,
                0, 0, 0, 0, DF, (long)BT * FF_SZ, 2, 2, 0);
        silu_split_kernel<<<(BT * FF_SZ / 2 + 255) / 256, 256>>>(
            f13, (u32*)f1h, (u32*)f1l, (long)BT * FF_SZ / 2);
        gemm_kn(f1h, f1l, w2h + l * DF, w2l + l * DF, x, BT, D_SZ, FF_SZ, FF_SZ, D_SZ, D_SZ,
                0, 0, 0, 0, 0, 0, 1, 1, 1);
    }

    // 4) final norm + lm_head (wide-tile path)
    rmsnorm_split_kernel<<<BT, 256>>>(x, final_norm, (u32*)hh, (u32*)hl);
    gemm_kn(hh, hl, lmh, lml, out, BT, V_SZ, D_SZ, D_SZ, V_SZ, V_SZ,
            0, 0, 0, 0, 0, 0, 1, 1, 0);
}

// round 14
// speedup vs baseline: 1.0125x; 1.0125x over previous
#include <cuda_runtime.h>
#include <math.h>

typedef unsigned short u16;
typedef unsigned int   u32;

// ---------------- problem constants ----------------
#define B_SZ 2
#define T_SZ 1024
#define D_SZ 1024
#define H_SZ 16
#define DH_SZ 64
#define FF_SZ 4096
#define L_SZ 2
#define V_SZ 32000
#define M_BLK 32
#define BS_SZ 32
#define TOPK 8
#define KEEP 128
#define EPSF 1e-6f
#define PI_D 3.14159265358979323846

// ---------------- fp32 scratch ----------------
__device__ float d_x  [B_SZ*T_SZ*D_SZ];
__device__ float d_h  [B_SZ*T_SZ*D_SZ];
__device__ float d_qkv[3*B_SZ*T_SZ*D_SZ];            // contiguous q|k|v (v section unused)
__device__ float d_o  [B_SZ*T_SZ*D_SZ];              // unused (planes only), kept for layout
__device__ float d_sc [(size_t)B_SZ*H_SZ*T_SZ*T_SZ];
__device__ float d_f13[2*B_SZ*T_SZ*FF_SZ];           // contiguous f1|f3
__device__ float d_G  [T_SZ*T_SZ];
__device__ float d_gk [T_SZ];
__device__ float d_rho[B_SZ*T_SZ];
__device__ int   d_sel[B_SZ*M_BLK];

// ---------------- bf16 hi/lo planes ----------------
__device__ u16 d_xh  [B_SZ*T_SZ*D_SZ],   d_xl  [B_SZ*T_SZ*D_SZ];
__device__ u16 d_Gh  [T_SZ*T_SZ],        d_Gl  [T_SZ*T_SZ];
__device__ u16 d_hh  [B_SZ*T_SZ*D_SZ],   d_hl  [B_SZ*T_SZ*D_SZ];
__device__ u16 d_qkvh[3*B_SZ*T_SZ*D_SZ], d_qkvl[3*B_SZ*T_SZ*D_SZ];
__device__ u16 d_sch [(size_t)B_SZ*H_SZ*T_SZ*T_SZ], d_scl[(size_t)B_SZ*H_SZ*T_SZ*T_SZ];
__device__ u16 d_oh  [B_SZ*T_SZ*D_SZ],   d_ol  [B_SZ*T_SZ*D_SZ];
__device__ u16 d_f1h [B_SZ*T_SZ*FF_SZ],  d_f1l [B_SZ*T_SZ*FF_SZ];
// weights (natural [K][N] layout planes)
__device__ u16 d_wqkvh[L_SZ*3*D_SZ*D_SZ], d_wqkvl[L_SZ*3*D_SZ*D_SZ];
__device__ u16 d_woh [L_SZ*D_SZ*D_SZ],   d_wol [L_SZ*D_SZ*D_SZ];
__device__ u16 d_w13h[L_SZ*2*D_SZ*FF_SZ], d_w13l[L_SZ*2*D_SZ*FF_SZ];
__device__ u16 d_w2h [L_SZ*FF_SZ*D_SZ],  d_w2l [L_SZ*FF_SZ*D_SZ];
__device__ u16 d_lmh [(size_t)D_SZ*V_SZ], d_lml [(size_t)D_SZ*V_SZ];

// ---------------- split helpers ----------------
__device__ __forceinline__ void split2(float v0, float v1, u32 &hi, u32 &lo)
{
    asm("cvt.rn.bf16x2.f32 %0, %1, %2;" : "=r"(hi) : "f"(v1), "f"(v0));
    float h0 = __int_as_float(hi << 16);
    float h1 = __int_as_float(hi & 0xffff0000u);
    asm("cvt.rn.bf16x2.f32 %0, %1, %2;" : "=r"(lo) : "f"(v1 - h1), "f"(v0 - h0));
}

__global__ __launch_bounds__(256) void split_kernel(const float* __restrict__ in,
                                                    uint2* __restrict__ hi, uint2* __restrict__ lo,
                                                    long n4)
{
    long idx = (long)blockIdx.x * blockDim.x + threadIdx.x;
    if (idx >= n4) return;
    float4 v = reinterpret_cast<const float4*>(in)[idx];
    u32 h0, l0, h1, l1;
    split2(v.x, v.y, h0, l0);
    split2(v.z, v.w, h1, l1);
    hi[idx] = make_uint2(h0, h1);
    lo[idx] = make_uint2(l0, l1);
}

#define MMA_BF16(ACC, A, B0, B1)                                                 \
    asm volatile(                                                                \
        "mma.sync.aligned.m16n8k16.row.col.f32.bf16.bf16.f32 "                   \
        "{%0,%1,%2,%3}, {%4,%5,%6,%7}, {%8,%9}, {%0,%1,%2,%3};"                  \
        : "+f"(ACC[0]), "+f"(ACC[1]), "+f"(ACC[2]), "+f"(ACC[3])                 \
        : "r"(A[0]), "r"(A[1]), "r"(A[2]), "r"(A[3]), "r"(B0), "r"(B1))

#define LDSM4(R, ADDR)                                                           \
    asm volatile("ldmatrix.sync.aligned.m8n8.x4.shared.b16 {%0,%1,%2,%3},[%4];"  \
        : "=r"(R[0]), "=r"(R[1]), "=r"(R[2]), "=r"(R[3]) : "r"(ADDR))

#define LDSM4T(R0, R1, R2, R3, ADDR)                                             \
    asm volatile("ldmatrix.sync.aligned.m8n8.x4.trans.shared.b16 {%0,%1,%2,%3},[%4];" \
        : "=r"(R0), "=r"(R1), "=r"(R2), "=r"(R3) : "r"(ADDR))

// =====================================================================
// bf16 hi/lo 3-term GEMM, 3-stage cp.async pipeline, block-sparse modes.
// smode 0: dense. smode 1: scores (skip dead output tiles).
// smode 2: attn@V (iterate only live 32-wide K blocks).
// emode 0: fp32 C (+ planes if Chp). emode 1: QKV — zh<2 fp32 only,
//          zh==2 planes only. emode 2: planes only (no fp32 C write).
// BNK=true: B stored row-major [N][K].
// =====================================================================
#define LDA_S 40   // u16 stride (80B)
#define NSTG 3

template<bool BNK>
__global__ __launch_bounds__(256, 2)
void bf16_gemm_kernel(const u16* __restrict__ Ahi, const u16* __restrict__ Alo,
                      const u16* __restrict__ Bhi, const u16* __restrict__ Blo,
                      float* __restrict__ Cg,
                      int K, int lda, int ldb, int ldc,
                      long sAb, long sBb, long sCb, long sAh, long sBh, long sCh,
                      int Hdim, int beta,
                      const int* __restrict__ selp, int smode, int emode,
                      u32* __restrict__ Chp, u32* __restrict__ Clp)
{
    constexpr int BM = 128, BK = 32, BN = 64, WM = 4, WN = 2;
    constexpr int AM = 2, AN = 4;
    constexpr int LDB_S = BNK ? LDA_S : (BN + 8);
    constexpr int A_PL  = BM * LDA_S;
    constexpr int B_PL  = BNK ? (BN * LDA_S) : (BK * LDB_S);
    constexpr int STAGE = 2 * A_PL + 2 * B_PL;

    extern __shared__ u16 smu[];
    __shared__ int klist[129];
    __shared__ int kcnt;

    int z = blockIdx.z, zb = z / Hdim, zh = z % Hdim;
    const int tid = threadIdx.x, lane = tid & 31, w = tid >> 5;
    const int row0 = blockIdx.y * BM, col0 = blockIdx.x * BN;

    if (smode == 1) {
        int qbmin = row0 >> 5, qbmax = qbmin + 3;
        bool need = false;
#pragma unroll
        for (int i = 0; i < 2; i++) {
            int kb = (col0 >> 5) + i;
            if (kb <= qbmax && (selp[zb * M_BLK + kb] || kb >= qbmin)) need = true;
        }
        if (!need) return;
    }
    if (tid == 0) {
        int c = 0;
        if (smode == 2) {
            int qbmin = row0 >> 5, qbmax = qbmin + 3;
            for (int kb = 0; kb < K / 32; kb++)
                if (kb <= qbmax && (selp[zb * M_BLK + kb] || kb >= qbmin))
                    klist[c++] = kb * 32;
        } else {
            for (int t = 0; t < K / BK; t++) klist[c++] = t * BK;
        }
        kcnt = c;
    }
    __syncthreads();
    const int ntiles = kcnt;

    const u16* Ah = Ahi + zb * sAb + zh * sAh;
    const u16* Al = Alo + zb * sAb + zh * sAh;
    const u16* Bh = Bhi + zb * sBb + zh * sBh;
    const u16* Bl = Blo + zb * sBb + zh * sBh;
    float*     C  = Cg  + zb * sCb + zh * sCh;
    u32* Ch = Chp ? Chp + (zb * sCb + zh * sCh) / 2 : (u32*)0;
    u32* Cl = Clp ? Clp + (zb * sCb + zh * sCh) / 2 : (u32*)0;

    // epilogue write selection
    bool wantF = (emode == 0) || (emode == 1 && zh < 2);
    bool wantP = (Ch != 0) && ((emode == 0) || (emode == 2) || (emode == 1 && zh == 2));

    const int wm = w % WM, wn = w / WM;
    const int mW = wm * (BM / WM), nW = wn * (BN / WN);

    float acc[AM][AN][4];
#pragma unroll
    for (int i = 0; i < AM; i++)
#pragma unroll
        for (int j = 0; j < AN; j++)
#pragma unroll
            for (int r = 0; r < 4; r++) acc[i][j][r] = 0.f;

    auto cpa = [&](u16* dst, const u16* src) {
        u32 d = (u32)__cvta_generic_to_shared(dst);
        asm volatile("cp.async.cg.shared.global [%0],[%1],16;\n" :: "r"(d), "l"(src));
    };
    auto load_tile = [&](int s, int kt) {
        u16* base = smu + s * STAGE;
#pragma unroll
        for (int i = 0; i < 2; i++) {
            int ch = tid + i * 256;
            int r = ch >> 2, c = ch & 3;
            size_t go = (size_t)(row0 + r) * lda + kt + c * 8;
            cpa(base + r * LDA_S + c * 8,        Ah + go);
            cpa(base + A_PL + r * LDA_S + c * 8, Al + go);
        }
        u16* bb = base + 2 * A_PL;
        if (BNK) {
            int r = tid >> 2, c = tid & 3;
            size_t go = (size_t)(col0 + r) * ldb + kt + c * 8;
            cpa(bb + r * LDA_S + c * 8,        Bh + go);
            cpa(bb + B_PL + r * LDA_S + c * 8, Bl + go);
        } else {
            int r = tid >> 3, c = tid & 7;
            size_t go = (size_t)(kt + r) * ldb + col0 + c * 8;
            cpa(bb + r * LDB_S + c * 8,        Bh + go);
            cpa(bb + B_PL + r * LDB_S + c * 8, Bl + go);
        }
    };

    // 3-stage pipeline: up to 2 tiles in flight while computing one.
    load_tile(0, klist[0]);
    asm volatile("cp.async.commit_group;\n" ::: "memory");
    if (ntiles > 1) {
        load_tile(1, klist[1]);
        asm volatile("cp.async.commit_group;\n" ::: "memory");
    }

    for (int t = 0; t < ntiles; t++) {
        int s = t % NSTG;
        if (t + 1 < ntiles) {
            asm volatile("cp.async.wait_group 1;\n" ::: "memory");
        } else {
            asm volatile("cp.async.wait_group 0;\n" ::: "memory");
        }
        __syncthreads();
        if (t + 2 < ntiles) {
            load_tile((t + 2) % NSTG, klist[t + 2]);
            asm volatile("cp.async.commit_group;\n" ::: "memory");
        }

        const u16* sa = smu + s * STAGE;
        const u16* sb = sa + 2 * A_PL;
#pragma unroll
        for (int ks = 0; ks < 2; ks++) {
            u32 ah[AM][4], al[AM][4], bh[AN][2], bl[AN][2];
            int arow = ((lane >> 3) & 1) * 8 + (lane & 7);
            int acol = ks * 16 + (lane >> 4) * 8;
#pragma unroll
            for (int am = 0; am < AM; am++) {
                const u16* p = sa + (mW + am * 16 + arow) * LDA_S + acol;
                u32 addr = (u32)__cvta_generic_to_shared(p);
                LDSM4(ah[am], addr);
                LDSM4(al[am], addr + A_PL * 2);
            }
            if (BNK) {
                int brow = ((lane >> 4) & 1) * 8 + (lane & 7);
                int bcol = ks * 16 + ((lane >> 3) & 1) * 8;
#pragma unroll
                for (int a2 = 0; a2 < AN / 2; a2++) {
                    const u16* p = sb + (nW + a2 * 16 + brow) * LDA_S + bcol;
                    u32 addr = (u32)__cvta_generic_to_shared(p);
                    asm volatile("ldmatrix.sync.aligned.m8n8.x4.shared.b16 {%0,%1,%2,%3},[%4];"
                        : "=r"(bh[2*a2][0]), "=r"(bh[2*a2][1]),
                          "=r"(bh[2*a2+1][0]), "=r"(bh[2*a2+1][1]) : "r"(addr));
                    asm volatile("ldmatrix.sync.aligned.m8n8.x4.shared.b16 {%0,%1,%2,%3},[%4];"
                        : "=r"(bl[2*a2][0]), "=r"(bl[2*a2][1]),
                          "=r"(bl[2*a2+1][0]), "=r"(bl[2*a2+1][1]) : "r"(addr + B_PL * 2));
                }
            } else {
                int brow = ks * 16 + ((lane >> 3) & 1) * 8 + (lane & 7);
                int bcol = (lane >> 4) * 8;
#pragma unroll
                for (int a2 = 0; a2 < AN / 2; a2++) {
                    const u16* p = sb + brow * LDB_S + nW + a2 * 16 + bcol;
                    u32 addr = (u32)__cvta_generic_to_shared(p);
                    LDSM4T(bh[2*a2][0], bh[2*a2][1], bh[2*a2+1][0], bh[2*a2+1][1], addr);
                    LDSM4T(bl[2*a2][0], bl[2*a2][1], bl[2*a2+1][0], bl[2*a2+1][1],
                           addr + B_PL * 2);
                }
            }
#pragma unroll
            for (int am = 0; am < AM; am++)
#pragma unroll
                for (int an = 0; an < AN; an++) {
                    MMA_BF16(acc[am][an], ah[am], bh[an][0], bh[an][1]);
                    MMA_BF16(acc[am][an], ah[am], bl[an][0], bl[an][1]);
                    MMA_BF16(acc[am][an], al[am], bh[an][0], bh[an][1]);
                }
        }
        __syncthreads();
    }

#pragma unroll
    for (int am = 0; am < AM; am++)
#pragma unroll
        for (int an = 0; an < AN; an++) {
            int r = row0 + mW + am * 16 + (lane >> 2);
            int c = col0 + nW + an * 8 + (lane & 3) * 2;
            size_t i0 = (size_t)r * ldc + c;
            size_t i1 = (size_t)(r + 8) * ldc + c;
            float2 v0 = make_float2(acc[am][an][0], acc[am][an][1]);
            float2 v1 = make_float2(acc[am][an][2], acc[am][an][3]);
            if (beta) {
                float2 p0 = *reinterpret_cast<const float2*>(C + i0);
                float2 p1 = *reinterpret_cast<const float2*>(C + i1);
                v0.x += p0.x; v0.y += p0.y; v1.x += p1.x; v1.y += p1.y;
            }
            if (wantF) {
                *reinterpret_cast<float2*>(C + i0) = v0;
                *reinterpret_cast<float2*>(C + i1) = v1;
            }
            if (wantP) {
                u32 hh_, ll_;
                split2(v0.x, v0.y, hh_, ll_);
                Ch[i0 >> 1] = hh_; Cl[i0 >> 1] = ll_;
                split2(v1.x, v1.y, hh_, ll_);
                Ch[i1 >> 1] = hh_; Cl[i1 >> 1] = ll_;
            }
        }
}

// ---------------- elementwise kernels ----------------
__global__ void embed_split_kernel(const int* __restrict__ ids, const float* __restrict__ emb,
                                   float* __restrict__ x, u32* __restrict__ xh, u32* __restrict__ xl)
{
    int idx = blockIdx.x * blockDim.x + threadIdx.x;   // B*T*D/2
    int d2 = idx & 511;
    int bt = idx >> 9;
    float2 v = *reinterpret_cast<const float2*>(emb + (size_t)ids[bt] * D_SZ + d2 * 2);
    *reinterpret_cast<float2*>(x + (size_t)bt * D_SZ + d2 * 2) = v;
    u32 h, l;
    split2(v.x, v.y, h, l);
    xh[idx] = h; xl[idx] = l;
}

__global__ void dirichlet_kernel(float* __restrict__ g)
{
    int d = blockIdx.x * blockDim.x + threadIdx.x;
    if (d >= T_SZ) return;
    double s = 0.0;
    for (int k = 1; k < KEEP; k++)
        s += cos(2.0 * PI_D * (double)k * (double)d / (double)T_SZ);
    g[d] = (float)((1.0 + 2.0 * s) / (double)T_SZ);
}

__global__ void buildG_kernel(const float* __restrict__ g, float* __restrict__ G)
{
    int i = blockIdx.x * blockDim.x + threadIdx.x;
    int t = i >> 10, s = i & (T_SZ - 1);
    G[i] = g[(t - s) & (T_SZ - 1)];
}

__global__ __launch_bounds__(256) void rho_kernel(const float* __restrict__ hlp,
                                                  const float* __restrict__ x,
                                                  float* __restrict__ rho)
{
    size_t row = (size_t)blockIdx.x * D_SZ;
    int tid = threadIdx.x;
    float s1 = 0.f, s2 = 0.f;
#pragma unroll
    for (int i = 0; i < 4; i++) {
        float a = hlp[row + tid + i * 256];
        float b = x  [row + tid + i * 256];
        s1 += a * a; s2 += b * b;
    }
    for (int o = 16; o > 0; o >>= 1) {
        s1 += __shfl_xor_sync(0xffffffffu, s1, o);
        s2 += __shfl_xor_sync(0xffffffffu, s2, o);
    }
    __shared__ float r1[8], r2[8];
    if ((tid & 31) == 0) { r1[tid >> 5] = s1; r2[tid >> 5] = s2; }
    __syncthreads();
    if (tid == 0) {
        float t1 = 0.f, t2 = 0.f;
        for (int i = 0; i < 8; i++) { t1 += r1[i]; t2 += r2[i]; }
        rho[blockIdx.x] = t1 / (t2 + EPSF);
    }
}

__global__ void select_blocks(const float* __restrict__ rho, int* __restrict__ sel)
{
    __shared__ float bq[B_SZ][M_BLK];
    int tid = threadIdx.x;
    if (tid < B_SZ * M_BLK) {
        int b = tid >> 5, m = tid & 31;
        float s = 0.f;
        for (int i = 0; i < BS_SZ; i++) s += rho[b * T_SZ + m * BS_SZ + i];
        bq[b][m] = s * (1.f / BS_SZ);
        sel[tid] = 0;
    }
    __syncthreads();
    if (tid < B_SZ) {
        int b = tid;
        bool picked[M_BLK];
        for (int m = 0; m < M_BLK; m++) picked[m] = false;
        for (int it = 0; it < TOPK; it++) {
            int best = -1; float bv = -3.4e38f;
            for (int m = 0; m < M_BLK; m++)
                if (!picked[m] && bq[b][m] > bv) { bv = bq[b][m]; best = m; }
            picked[best] = true;
            sel[b * M_BLK + best] = 1;
        }
    }
}

__global__ __launch_bounds__(256) void rmsnorm_split_kernel(
    const float* __restrict__ x, const float* __restrict__ w,
    u32* __restrict__ yh, u32* __restrict__ yl)
{
    size_t row = (size_t)blockIdx.x * D_SZ;
    int tid = threadIdx.x;
    float4 v = reinterpret_cast<const float4*>(x + row)[tid];
    float s = v.x * v.x + v.y * v.y + v.z * v.z + v.w * v.w;
    for (int o = 16; o > 0; o >>= 1) s += __shfl_xor_sync(0xffffffffu, s, o);
    __shared__ float red[8];
    if ((tid & 31) == 0) red[tid >> 5] = s;
    __syncthreads();
    float tot = 0.f;
    for (int i = 0; i < 8; i++) tot += red[i];
    float r = rsqrtf(tot * (1.f / D_SZ) + EPSF);
    float4 wv = reinterpret_cast<const float4*>(w)[tid];
    u32 h0, l0, h1, l1;
    split2(v.x * r * wv.x, v.y * r * wv.y, h0, l0);
    split2(v.z * r * wv.z, v.w * r * wv.w, h1, l1);
    size_t c = row / 2 + tid * 2;
    yh[c] = h0; yh[c + 1] = h1;
    yl[c] = l0; yl[c + 1] = l1;
}

__global__ void rope_split_kernel(const float* __restrict__ qkv,
                                  u32* __restrict__ qkvh, u32* __restrict__ qkvl)
{
    const int QK = B_SZ * T_SZ * D_SZ;
    int idx = blockIdx.x * blockDim.x + threadIdx.x;   // B*T*H*16
    int j2 = idx & 15;
    int h  = (idx >> 4) & (H_SZ - 1);
    int t  = (idx >> 8) & (T_SZ - 1);
    int b  = idx >> 18;
    int e0 = 2 * j2;
    float inv0 = (float)(1.0 / pow(10000.0, (double)(2 * e0)     / (double)DH_SZ));
    float inv1 = (float)(1.0 / pow(10000.0, (double)(2 * (e0+1)) / (double)DH_SZ));
    float c0 = cosf(t * inv0), s0 = sinf(t * inv0);
    float c1 = cosf(t * inv1), s1 = sinf(t * inv1);
    size_t base = ((size_t)(b * T_SZ + t)) * D_SZ + h * DH_SZ + e0;
    float2 qa = *reinterpret_cast<const float2*>(qkv + base);
    float2 qb = *reinterpret_cast<const float2*>(qkv + base + 32);
    float2 ka = *reinterpret_cast<const float2*>(qkv + QK + base);
    float2 kb = *reinterpret_cast<const float2*>(qkv + QK + base + 32);
    float q0 = qa.x * c0 - qb.x * s0, q1 = qa.y * c1 - qb.y * s1;
    float q2 = qb.x * c0 + qa.x * s0, q3 = qb.y * c1 + qa.y * s1;
    float k0 = ka.x * c0 - kb.x * s0, k1 = ka.y * c1 - kb.y * s1;
    float k2 = kb.x * c0 + ka.x * s0, k3 = kb.y * c1 + ka.y * s1;
    size_t p0 = base >> 1, p1 = (base + 32) >> 1;
    const size_t QK2 = QK / 2;
    u32 hh_, ll_;
    split2(q0, q1, hh_, ll_); qkvh[p0] = hh_;       qkvl[p0] = ll_;
    split2(q2, q3, hh_, ll_); qkvh[p1] = hh_;       qkvl[p1] = ll_;
    split2(k0, k1, hh_, ll_); qkvh[QK2 + p0] = hh_; qkvl[QK2 + p0] = ll_;
    split2(k2, k3, hh_, ll_); qkvh[QK2 + p1] = hh_; qkvl[QK2 + p1] = ll_;
}

__global__ __launch_bounds__(256) void masked_softmax_split_kernel(
    const float* __restrict__ s, const int* __restrict__ sel,
    u32* __restrict__ ph, u32* __restrict__ pl)
{
    int gid = blockIdx.x;
    int tq = gid & (T_SZ - 1);
    int b  = gid / (H_SZ * T_SZ);
    size_t row = (size_t)gid * T_SZ;
    int tid = threadIdx.x;
    const float scale = 0.125f;
    int qblk  = tq >> 5;
    int qbmin = (tq >> 7) << 2;
    int qbmax = qbmin + 3;

    float v[4];
    bool wlive[2];
    float mx = -3.4e38f;
#pragma unroll
    for (int i = 0; i < 2; i++) {
        int p  = tid + i * 256;
        int kb = p >> 4;
        bool blive = (kb <= qblk) && (sel[b * M_BLK + kb] || kb == qblk);
        wlive[i]   = (kb <= qbmax) && (sel[b * M_BLK + kb] || kb >= qbmin);
        float2 vv = make_float2(-1e9f, -1e9f);
        if (blive) vv = *reinterpret_cast<const float2*>(s + row + 2 * p);
        int e0 = 2 * p;
        v[2*i]   = (blive && e0     <= tq) ? vv.x * scale : -1e9f;
        v[2*i+1] = (blive && e0 + 1 <= tq) ? vv.y * scale : -1e9f;
        mx = fmaxf(mx, fmaxf(v[2*i], v[2*i+1]));
    }
    for (int o = 16; o > 0; o >>= 1) mx = fmaxf(mx, __shfl_xor_sync(0xffffffffu, mx, o));
    __shared__ float red[8];
    if ((tid & 31) == 0) red[tid >> 5] = mx;
    __syncthreads();
    float m = red[0];
    for (int i = 1; i < 8; i++) m = fmaxf(m, red[i]);
    __syncthreads();
    float sum = 0.f;
#pragma unroll
    for (int i = 0; i < 4; i++) { v[i] = expf(v[i] - m); sum += v[i]; }
    for (int o = 16; o > 0; o >>= 1) sum += __shfl_xor_sync(0xffffffffu, sum, o);
    if ((tid & 31) == 0) red[tid >> 5] = sum;
    __syncthreads();
    float tot = 0.f;
    for (int i = 0; i < 8; i++) tot += red[i];
    float inv = 1.f / tot;
    size_t prow = row >> 1;
#pragma unroll
    for (int i = 0; i < 2; i++) {
        if (!wlive[i]) continue;
        int p = tid + i * 256;
        u32 hh_, ll_;
        split2(v[2*i] * inv, v[2*i+1] * inv, hh_, ll_);
        ph[prow + p] = hh_; pl[prow + p] = ll_;
    }
}

__global__ __launch_bounds__(256) void silu_split_kernel(const float* __restrict__ f13,
                                                         u32* __restrict__ gh, u32* __restrict__ gl,
                                                         long n2)
{
    long idx = (long)blockIdx.x * blockDim.x + threadIdx.x;
    if (idx >= n2) return;
    const long F3OFF = (long)B_SZ * T_SZ * FF_SZ / 2;
    float2 a = reinterpret_cast<const float2*>(f13)[idx];
    float2 g = reinterpret_cast<const float2*>(f13)[F3OFF + idx];
    float y0 = a.x / (1.f + expf(-a.x)) * g.x;
    float y1 = a.y / (1.f + expf(-a.y)) * g.y;
    u32 h, l;
    split2(y0, y1, h, l);
    gh[idx] = h; gl[idx] = l;
}

// ---------------- host launchers ----------------
static const int SMEM_KN64 = NSTG * (2*128*LDA_S + 2*32*(64+8)) * 2;
static const int SMEM_NK64 = NSTG * (2*128*LDA_S + 2*64*LDA_S)  * 2;

static void gemm_kn(const u16* Ah, const u16* Al, const u16* Bh, const u16* Bl, float* C,
                    int M, int N, int K, int lda, int ldb, int ldc,
                    long sAb, long sBb, long sCb, long sAh, long sBh, long sCh,
                    int Hdim, int nb, int beta,
                    const int* sel = 0, int smode = 0, u16* Ch = 0, u16* Cl = 0,
                    int emode = 0)
{
    dim3 grid(N / 64, M / 128, nb);
    bf16_gemm_kernel<false><<<grid, 256, SMEM_KN64>>>(
        Ah, Al, Bh, Bl, C, K, lda, ldb, ldc, sAb, sBb, sCb, sAh, sBh, sCh, Hdim, beta,
        sel, smode, emode, (u32*)Ch, (u32*)Cl);
}

static void gemm_nk(const u16* Ah, const u16* Al, const u16* Bh, const u16* Bl, float* C,
                    int M, int N, int K, int lda, int ldb, int ldc,
                    long sAb, long sBb, long sCb, long sAh, long sBh, long sCh,
                    int Hdim, int nb, int beta, const int* sel, int smode)
{
    dim3 grid(N / 64, M / 128, nb);
    bf16_gemm_kernel<true><<<grid, 256, SMEM_NK64>>>(
        Ah, Al, Bh, Bl, C, K, lda, ldb, ldc, sAb, sBb, sCb, sAh, sBh, sCh, Hdim, beta,
        sel, smode, 0, (u32*)0, (u32*)0);
}

static void split(const float* in, u16* hi, u16* lo, long n)
{
    long n4 = n / 4;
    split_kernel<<<(unsigned)((n4 + 255) / 256), 256>>>(in, (uint2*)hi, (uint2*)lo, n4);
}

extern "C" void kernel_launch(void* const* d_in, const int* in_sizes, int n_in,
                              void* d_out, int out_size)
{
    const int*   ids        = (const int*)  d_in[0];
    const float* emb        = (const float*)d_in[1];
    const float* wq         = (const float*)d_in[2];
    const float* wk         = (const float*)d_in[3];
    const float* wv         = (const float*)d_in[4];
    const float* wo         = (const float*)d_in[5];
    const float* w1         = (const float*)d_in[6];
    const float* w2         = (const float*)d_in[7];
    const float* w3         = (const float*)d_in[8];
    const float* attn_norm  = (const float*)d_in[9];
    const float* ffn_norm   = (const float*)d_in[10];
    const float* final_norm = (const float*)d_in[11];
    const float* lm_head    = (const float*)d_in[12];
    float* out = (float*)d_out;

    static bool attrs_set = false;
    if (!attrs_set) {
        cudaFuncSetAttribute(bf16_gemm_kernel<false>,
                             cudaFuncAttributeMaxDynamicSharedMemorySize, SMEM_KN64);
        cudaFuncSetAttribute(bf16_gemm_kernel<true>,
                             cudaFuncAttributeMaxDynamicSharedMemorySize, SMEM_NK64);
        attrs_set = true;
    }

    float *x, *h, *qkv, *o, *sc, *f13, *G, *gk, *rho;
    int* sel;
    cudaGetSymbolAddress((void**)&x,   d_x);
    cudaGetSymbolAddress((void**)&h,   d_h);
    cudaGetSymbolAddress((void**)&qkv, d_qkv);
    cudaGetSymbolAddress((void**)&o,   d_o);
    cudaGetSymbolAddress((void**)&sc,  d_sc);
    cudaGetSymbolAddress((void**)&f13, d_f13);
    cudaGetSymbolAddress((void**)&G,   d_G);
    cudaGetSymbolAddress((void**)&gk,  d_gk);
    cudaGetSymbolAddress((void**)&rho, d_rho);
    cudaGetSymbolAddress((void**)&sel, d_sel);

    u16 *xh,*xl,*Gh,*Gl,*hh,*hl,*qkvh,*qkvl,*sch,*scl,*oh,*ol,*f1h,*f1l;
    u16 *wqkvh,*wqkvl,*woh,*wol,*w13h,*w13l,*w2h,*w2l,*lmh,*lml;
    cudaGetSymbolAddress((void**)&xh, d_xh);     cudaGetSymbolAddress((void**)&xl, d_xl);
    cudaGetSymbolAddress((void**)&Gh, d_Gh);     cudaGetSymbolAddress((void**)&Gl, d_Gl);
    cudaGetSymbolAddress((void**)&hh, d_hh);     cudaGetSymbolAddress((void**)&hl, d_hl);
    cudaGetSymbolAddress((void**)&qkvh, d_qkvh); cudaGetSymbolAddress((void**)&qkvl, d_qkvl);
    cudaGetSymbolAddress((void**)&sch, d_sch);   cudaGetSymbolAddress((void**)&scl, d_scl);
    cudaGetSymbolAddress((void**)&oh, d_oh);     cudaGetSymbolAddress((void**)&ol, d_ol);
    cudaGetSymbolAddress((void**)&f1h, d_f1h);   cudaGetSymbolAddress((void**)&f1l, d_f1l);
    cudaGetSymbolAddress((void**)&wqkvh, d_wqkvh); cudaGetSymbolAddress((void**)&wqkvl, d_wqkvl);
    cudaGetSymbolAddress((void**)&woh, d_woh);   cudaGetSymbolAddress((void**)&wol, d_wol);
    cudaGetSymbolAddress((void**)&w13h, d_w13h); cudaGetSymbolAddress((void**)&w13l, d_w13l);
    cudaGetSymbolAddress((void**)&w2h, d_w2h);   cudaGetSymbolAddress((void**)&w2l, d_w2l);
    cudaGetSymbolAddress((void**)&lmh, d_lmh);   cudaGetSymbolAddress((void**)&lml, d_lml);

    const int  BT = B_SZ * T_SZ;
    const long DD = (long)D_SZ * D_SZ;
    const long DF = (long)D_SZ * FF_SZ;
    const long QK = (long)BT * D_SZ;

    // weight splits into concatenated plane buffers
    for (int l = 0; l < L_SZ; l++) {
        split(wq + l * DD, wqkvh + (3 * l + 0) * DD, wqkvl + (3 * l + 0) * DD, DD);
        split(wk + l * DD, wqkvh + (3 * l + 1) * DD, wqkvl + (3 * l + 1) * DD, DD);
        split(wv + l * DD, wqkvh + (3 * l + 2) * DD, wqkvl + (3 * l + 2) * DD, DD);
        split(w1 + l * DF, w13h + (2 * l + 0) * DF, w13l + (2 * l + 0) * DF, DF);
        split(w3 + l * DF, w13h + (2 * l + 1) * DF, w13l + (2 * l + 1) * DF, DF);
    }
    split(wo, woh, wol, (long)L_SZ * DD);
    split(w2, w2h, w2l, (long)L_SZ * DF);
    split(lm_head, lmh, lml, (long)D_SZ * V_SZ);

    // 1) embedding (+split)
    embed_split_kernel<<<(B_SZ * T_SZ * D_SZ / 2) / 256, 256>>>(
        ids, emb, x, (u32*)xh, (u32*)xl);

    // 2) low-pass quality -> block selection
    dirichlet_kernel<<<T_SZ / 256, 256>>>(gk);
    buildG_kernel<<<(T_SZ * T_SZ) / 256, 256>>>(gk, G);
    split(G, Gh, Gl, (long)T_SZ * T_SZ);
    gemm_kn(Gh, Gl, xh, xl, h, T_SZ, D_SZ, T_SZ, T_SZ, D_SZ, D_SZ,
            0, (long)T_SZ * D_SZ, (long)T_SZ * D_SZ, 0, 0, 0, 1, B_SZ, 0);
    rho_kernel<<<BT, 256>>>(h, x, rho);
    select_blocks<<<1, 64>>>(rho, sel);

    // 3) transformer layers
    for (int l = 0; l < L_SZ; l++) {
        rmsnorm_split_kernel<<<BT, 256>>>(x, attn_norm + (size_t)l * D_SZ, (u32*)hh, (u32*)hl);

        // fused QKV (z in {0,1,2}): q,k fp32 only; v planes only (emode=1)
        gemm_kn(hh, hl, wqkvh + 3 * l * DD, wqkvl + 3 * l * DD, qkv,
                BT, D_SZ, D_SZ, D_SZ, D_SZ, D_SZ,
                0, 0, 0, 0, DD, QK, 3, 3, 0, 0, 0,
                (u16*)qkvh, (u16*)qkvl, /*emode=*/1);

        rope_split_kernel<<<(B_SZ * T_SZ * H_SZ * 16) / 256, 256>>>(
            qkv, (u32*)qkvh, (u32*)qkvl);

        gemm_nk(qkvh, qkvl, qkvh + QK, qkvl + QK, sc, T_SZ, T_SZ, DH_SZ,
                D_SZ, D_SZ, T_SZ,
                (long)T_SZ * D_SZ, (long)T_SZ * D_SZ, (long)H_SZ * T_SZ * T_SZ,
                DH_SZ, DH_SZ, (long)T_SZ * T_SZ, H_SZ, B_SZ * H_SZ, 0, sel, 1);

        masked_softmax_split_kernel<<<B_SZ * H_SZ * T_SZ, 256>>>(
            sc, sel, (u32*)sch, (u32*)scl);

        // attn@V: planes only (emode=2); fp32 o never read
        gemm_kn(sch, scl, qkvh + 2 * QK, qkvl + 2 * QK, o, T_SZ, DH_SZ, T_SZ,
                T_SZ, D_SZ, D_SZ,
                (long)H_SZ * T_SZ * T_SZ, (long)T_SZ * D_SZ, (long)T_SZ * D_SZ,
                (long)T_SZ * T_SZ, DH_SZ, DH_SZ, H_SZ, B_SZ * H_SZ, 0, sel, 2,
                oh, ol, /*emode=*/2);

        gemm_kn(oh, ol, woh + l * DD, wol + l * DD, x, BT, D_SZ, D_SZ, D_SZ, D_SZ, D_SZ,
                0, 0, 0, 0, 0, 0, 1, 1, 1);

        // FFN: fused w1/w3 (z in {0,1})
        rmsnorm_split_kernel<<<BT, 256>>>(x, ffn_norm + (size_t)l * D_SZ, (u32*)hh, (u32*)hl);
        gemm_kn(hh, hl, w13h + 2 * l * DF, w13l + 2 * l * DF, f13,
                BT, FF_SZ, D_SZ, D_SZ, FF_SZ, FF_SZ,
                0, 0, 0, 0, DF, (long)BT * FF_SZ, 2, 2, 0);
        silu_split_kernel<<<(BT * FF_SZ / 2 + 255) / 256, 256>>>(
            f13, (u32*)f1h, (u32*)f1l, (long)BT * FF_SZ / 2);
        gemm_kn(f1h, f1l, w2h + l * DF, w2l + l * DF, x, BT, D_SZ, FF_SZ, FF_SZ, D_SZ, D_SZ,
                0, 0, 0, 0, 0, 0, 1, 1, 1);
    }

    // 4) final norm + lm_head
    rmsnorm_split_kernel<<<BT, 256>>>(x, final_norm, (u32*)hh, (u32*)hl);
    gemm_kn(hh, hl, lmh, lml, out, BT, V_SZ, D_SZ, D_SZ, V_SZ, V_SZ,
            0, 0, 0, 0, 0, 0, 1, 1, 0);
}

// round 15
// speedup vs baseline: 1.0653x; 1.0521x over previous
#include <cuda_runtime.h>
#include <math.h>

typedef unsigned short u16;
typedef unsigned int   u32;

// ---------------- problem constants ----------------
#define B_SZ 2
#define T_SZ 1024
#define D_SZ 1024
#define H_SZ 16
#define DH_SZ 64
#define FF_SZ 4096
#define L_SZ 2
#define V_SZ 32000
#define M_BLK 32
#define BS_SZ 32
#define TOPK 8
#define KEEP 128
#define EPSF 1e-6f
#define PI_D 3.14159265358979323846

// ---------------- fp32 scratch ----------------
__device__ float d_x  [B_SZ*T_SZ*D_SZ];
__device__ float d_h  [B_SZ*T_SZ*D_SZ];
__device__ float d_qkv[3*B_SZ*T_SZ*D_SZ];            // contiguous q|k|v
__device__ float d_o  [B_SZ*T_SZ*D_SZ];
__device__ float d_sc [(size_t)B_SZ*H_SZ*T_SZ*T_SZ];
__device__ float d_f13[2*B_SZ*T_SZ*FF_SZ];           // contiguous f1|f3
__device__ float d_G  [T_SZ*T_SZ];
__device__ float d_gk [T_SZ];
__device__ float d_rho[B_SZ*T_SZ];
__device__ int   d_sel[B_SZ*M_BLK];

// ---------------- bf16 hi/lo planes ----------------
__device__ u16 d_xh  [B_SZ*T_SZ*D_SZ],   d_xl  [B_SZ*T_SZ*D_SZ];
__device__ u16 d_Gh  [T_SZ*T_SZ],        d_Gl  [T_SZ*T_SZ];
__device__ u16 d_hh  [B_SZ*T_SZ*D_SZ],   d_hl  [B_SZ*T_SZ*D_SZ];
__device__ u16 d_qkvh[3*B_SZ*T_SZ*D_SZ], d_qkvl[3*B_SZ*T_SZ*D_SZ];
__device__ u16 d_sch [(size_t)B_SZ*H_SZ*T_SZ*T_SZ], d_scl[(size_t)B_SZ*H_SZ*T_SZ*T_SZ];
__device__ u16 d_oh  [B_SZ*T_SZ*D_SZ],   d_ol  [B_SZ*T_SZ*D_SZ];
__device__ u16 d_f1h [B_SZ*T_SZ*FF_SZ],  d_f1l [B_SZ*T_SZ*FF_SZ];
// weights (natural [K][N] layout planes)
__device__ u16 d_wqkvh[L_SZ*3*D_SZ*D_SZ], d_wqkvl[L_SZ*3*D_SZ*D_SZ];
__device__ u16 d_woh [L_SZ*D_SZ*D_SZ],   d_wol [L_SZ*D_SZ*D_SZ];
__device__ u16 d_w13h[L_SZ*2*D_SZ*FF_SZ], d_w13l[L_SZ*2*D_SZ*FF_SZ];
__device__ u16 d_w2h [L_SZ*FF_SZ*D_SZ],  d_w2l [L_SZ*FF_SZ*D_SZ];
__device__ u16 d_lmh [(size_t)D_SZ*V_SZ], d_lml [(size_t)D_SZ*V_SZ];

// ---------------- split helpers ----------------
__device__ __forceinline__ void split2(float v0, float v1, u32 &hi, u32 &lo)
{
    asm("cvt.rn.bf16x2.f32 %0, %1, %2;" : "=r"(hi) : "f"(v1), "f"(v0));
    float h0 = __int_as_float(hi << 16);
    float h1 = __int_as_float(hi & 0xffff0000u);
    asm("cvt.rn.bf16x2.f32 %0, %1, %2;" : "=r"(lo) : "f"(v1 - h1), "f"(v0 - h0));
}

__global__ __launch_bounds__(256) void split_kernel(const float* __restrict__ in,
                                                    uint2* __restrict__ hi, uint2* __restrict__ lo,
                                                    long n4)
{
    long idx = (long)blockIdx.x * blockDim.x + threadIdx.x;
    if (idx >= n4) return;
    float4 v = reinterpret_cast<const float4*>(in)[idx];
    u32 h0, l0, h1, l1;
    split2(v.x, v.y, h0, l0);
    split2(v.z, v.w, h1, l1);
    hi[idx] = make_uint2(h0, h1);
    lo[idx] = make_uint2(l0, l1);
}

#define MMA_BF16(ACC, A, B0, B1)                                                 \
    asm volatile(                                                                \
        "mma.sync.aligned.m16n8k16.row.col.f32.bf16.bf16.f32 "                   \
        "{%0,%1,%2,%3}, {%4,%5,%6,%7}, {%8,%9}, {%0,%1,%2,%3};"                  \
        : "+f"(ACC[0]), "+f"(ACC[1]), "+f"(ACC[2]), "+f"(ACC[3])                 \
        : "r"(A[0]), "r"(A[1]), "r"(A[2]), "r"(A[3]), "r"(B0), "r"(B1))

#define LDSM4(R, ADDR)                                                           \
    asm volatile("ldmatrix.sync.aligned.m8n8.x4.shared.b16 {%0,%1,%2,%3},[%4];"  \
        : "=r"(R[0]), "=r"(R[1]), "=r"(R[2]), "=r"(R[3]) : "r"(ADDR))

#define LDSM4T(R0, R1, R2, R3, ADDR)                                             \
    asm volatile("ldmatrix.sync.aligned.m8n8.x4.trans.shared.b16 {%0,%1,%2,%3},[%4];" \
        : "=r"(R0), "=r"(R1), "=r"(R2), "=r"(R3) : "r"(ADDR))

// =====================================================================
// bf16 hi/lo 3-term GEMM, 3-stage cp.async pipeline, block-sparse modes.
// smode 0: dense. smode 1: scores (skip dead output tiles).
// smode 2: attn@V (iterate only live 32-wide K blocks).
// Optional Chp/Clp: epilogue also emits bf16 hi/lo planes (beta=0 only).
// BNK=true: B stored row-major [N][K].
// =====================================================================
#define LDA_S 40   // u16 stride (80B)
#define NSTG 3

template<bool BNK>
__global__ __launch_bounds__(256, 2)
void bf16_gemm_kernel(const u16* __restrict__ Ahi, const u16* __restrict__ Alo,
                      const u16* __restrict__ Bhi, const u16* __restrict__ Blo,
                      float* __restrict__ Cg,
                      int K, int lda, int ldb, int ldc,
                      long sAb, long sBb, long sCb, long sAh, long sBh, long sCh,
                      int Hdim, int beta,
                      const int* __restrict__ selp, int smode,
                      u32* __restrict__ Chp, u32* __restrict__ Clp)
{
    constexpr int BM = 128, BK = 32, BN = 64, WM = 4, WN = 2;
    constexpr int AM = 2, AN = 4;
    constexpr int LDB_S = BNK ? LDA_S : (BN + 8);
    constexpr int A_PL  = BM * LDA_S;
    constexpr int B_PL  = BNK ? (BN * LDA_S) : (BK * LDB_S);
    constexpr int STAGE = 2 * A_PL + 2 * B_PL;

    extern __shared__ u16 smu[];
    __shared__ int klist[129];
    __shared__ int kcnt;

    int z = blockIdx.z, zb = z / Hdim, zh = z % Hdim;
    const int tid = threadIdx.x, lane = tid & 31, w = tid >> 5;
    const int row0 = blockIdx.y * BM, col0 = blockIdx.x * BN;

    if (smode == 1) {
        int qbmin = row0 >> 5, qbmax = qbmin + 3;
        bool need = false;
#pragma unroll
        for (int i = 0; i < 2; i++) {
            int kb = (col0 >> 5) + i;
            if (kb <= qbmax && (selp[zb * M_BLK + kb] || kb >= qbmin)) need = true;
        }
        if (!need) return;
    }
    if (tid == 0) {
        int c = 0;
        if (smode == 2) {
            int qbmin = row0 >> 5, qbmax = qbmin + 3;
            for (int kb = 0; kb < K / 32; kb++)
                if (kb <= qbmax && (selp[zb * M_BLK + kb] || kb >= qbmin))
                    klist[c++] = kb * 32;
        } else {
            for (int t = 0; t < K / BK; t++) klist[c++] = t * BK;
        }
        kcnt = c;
    }
    __syncthreads();
    const int ntiles = kcnt;

    const u16* Ah = Ahi + zb * sAb + zh * sAh;
    const u16* Al = Alo + zb * sAb + zh * sAh;
    const u16* Bh = Bhi + zb * sBb + zh * sBh;
    const u16* Bl = Blo + zb * sBb + zh * sBh;
    float*     C  = Cg  + zb * sCb + zh * sCh;
    u32* Ch = Chp ? Chp + (zb * sCb + zh * sCh) / 2 : (u32*)0;
    u32* Cl = Clp ? Clp + (zb * sCb + zh * sCh) / 2 : (u32*)0;

    const int wm = w % WM, wn = w / WM;
    const int mW = wm * (BM / WM), nW = wn * (BN / WN);

    float acc[AM][AN][4];
#pragma unroll
    for (int i = 0; i < AM; i++)
#pragma unroll
        for (int j = 0; j < AN; j++)
#pragma unroll
            for (int r = 0; r < 4; r++) acc[i][j][r] = 0.f;

    auto cpa = [&](u16* dst, const u16* src) {
        u32 d = (u32)__cvta_generic_to_shared(dst);
        asm volatile("cp.async.cg.shared.global [%0],[%1],16;\n" :: "r"(d), "l"(src));
    };
    auto load_tile = [&](int s, int kt) {
        u16* base = smu + s * STAGE;
#pragma unroll
        for (int i = 0; i < 2; i++) {
            int ch = tid + i * 256;
            int r = ch >> 2, c = ch & 3;
            size_t go = (size_t)(row0 + r) * lda + kt + c * 8;
            cpa(base + r * LDA_S + c * 8,        Ah + go);
            cpa(base + A_PL + r * LDA_S + c * 8, Al + go);
        }
        u16* bb = base + 2 * A_PL;
        if (BNK) {
            int r = tid >> 2, c = tid & 3;
            size_t go = (size_t)(col0 + r) * ldb + kt + c * 8;
            cpa(bb + r * LDA_S + c * 8,        Bh + go);
            cpa(bb + B_PL + r * LDA_S + c * 8, Bl + go);
        } else {
            int r = tid >> 3, c = tid & 7;
            size_t go = (size_t)(kt + r) * ldb + col0 + c * 8;
            cpa(bb + r * LDB_S + c * 8,        Bh + go);
            cpa(bb + B_PL + r * LDB_S + c * 8, Bl + go);
        }
    };

    // 3-stage pipeline: up to 2 tiles in flight while computing one.
    load_tile(0, klist[0]);
    asm volatile("cp.async.commit_group;\n" ::: "memory");
    if (ntiles > 1) {
        load_tile(1, klist[1]);
        asm volatile("cp.async.commit_group;\n" ::: "memory");
    }

    for (int t = 0; t < ntiles; t++) {
        int s = t % NSTG;
        if (t + 1 < ntiles) {
            asm volatile("cp.async.wait_group 1;\n" ::: "memory");
        } else {
            asm volatile("cp.async.wait_group 0;\n" ::: "memory");
        }
        __syncthreads();
        if (t + 2 < ntiles) {
            load_tile((t + 2) % NSTG, klist[t + 2]);
            asm volatile("cp.async.commit_group;\n" ::: "memory");
        }

        const u16* sa = smu + s * STAGE;
        const u16* sb = sa + 2 * A_PL;
#pragma unroll
        for (int ks = 0; ks < 2; ks++) {
            u32 ah[AM][4], al[AM][4], bh[AN][2], bl[AN][2];
            int arow = ((lane >> 3) & 1) * 8 + (lane & 7);
            int acol = ks * 16 + (lane >> 4) * 8;
#pragma unroll
            for (int am = 0; am < AM; am++) {
                const u16* p = sa + (mW + am * 16 + arow) * LDA_S + acol;
                u32 addr = (u32)__cvta_generic_to_shared(p);
                LDSM4(ah[am], addr);
                LDSM4(al[am], addr + A_PL * 2);
            }
            if (BNK) {
                int brow = ((lane >> 4) & 1) * 8 + (lane & 7);
                int bcol = ks * 16 + ((lane >> 3) & 1) * 8;
#pragma unroll
                for (int a2 = 0; a2 < AN / 2; a2++) {
                    const u16* p = sb + (nW + a2 * 16 + brow) * LDA_S + bcol;
                    u32 addr = (u32)__cvta_generic_to_shared(p);
                    asm volatile("ldmatrix.sync.aligned.m8n8.x4.shared.b16 {%0,%1,%2,%3},[%4];"
                        : "=r"(bh[2*a2][0]), "=r"(bh[2*a2][1]),
                          "=r"(bh[2*a2+1][0]), "=r"(bh[2*a2+1][1]) : "r"(addr));
                    asm volatile("ldmatrix.sync.aligned.m8n8.x4.shared.b16 {%0,%1,%2,%3},[%4];"
                        : "=r"(bl[2*a2][0]), "=r"(bl[2*a2][1]),
                          "=r"(bl[2*a2+1][0]), "=r"(bl[2*a2+1][1]) : "r"(addr + B_PL * 2));
                }
            } else {
                int brow = ks * 16 + ((lane >> 3) & 1) * 8 + (lane & 7);
                int bcol = (lane >> 4) * 8;
#pragma unroll
                for (int a2 = 0; a2 < AN / 2; a2++) {
                    const u16* p = sb + brow * LDB_S + nW + a2 * 16 + bcol;
                    u32 addr = (u32)__cvta_generic_to_shared(p);
                    LDSM4T(bh[2*a2][0], bh[2*a2][1], bh[2*a2+1][0], bh[2*a2+1][1], addr);
                    LDSM4T(bl[2*a2][0], bl[2*a2][1], bl[2*a2+1][0], bl[2*a2+1][1],
                           addr + B_PL * 2);
                }
            }
#pragma unroll
            for (int am = 0; am < AM; am++)
#pragma unroll
                for (int an = 0; an < AN; an++) {
                    MMA_BF16(acc[am][an], ah[am], bh[an][0], bh[an][1]);
                    MMA_BF16(acc[am][an], ah[am], bl[an][0], bl[an][1]);
                    MMA_BF16(acc[am][an], al[am], bh[an][0], bh[an][1]);
                }
        }
        __syncthreads();
    }

#pragma unroll
    for (int am = 0; am < AM; am++)
#pragma unroll
        for (int an = 0; an < AN; an++) {
            int r = row0 + mW + am * 16 + (lane >> 2);
            int c = col0 + nW + an * 8 + (lane & 3) * 2;
            size_t i0 = (size_t)r * ldc + c;
            size_t i1 = (size_t)(r + 8) * ldc + c;
            float2 v0 = make_float2(acc[am][an][0], acc[am][an][1]);
            float2 v1 = make_float2(acc[am][an][2], acc[am][an][3]);
            if (beta) {
                float2 p0 = *reinterpret_cast<const float2*>(C + i0);
                float2 p1 = *reinterpret_cast<const float2*>(C + i1);
                v0.x += p0.x; v0.y += p0.y; v1.x += p1.x; v1.y += p1.y;
            }
            *reinterpret_cast<float2*>(C + i0) = v0;
            *reinterpret_cast<float2*>(C + i1) = v1;
            if (Ch) {
                u32 hh_, ll_;
                split2(v0.x, v0.y, hh_, ll_);
                Ch[i0 >> 1] = hh_; Cl[i0 >> 1] = ll_;
                split2(v1.x, v1.y, hh_, ll_);
                Ch[i1 >> 1] = hh_; Cl[i1 >> 1] = ll_;
            }
        }
}

// ---------------- elementwise kernels ----------------
__global__ void embed_split_kernel(const int* __restrict__ ids, const float* __restrict__ emb,
                                   float* __restrict__ x, u32* __restrict__ xh, u32* __restrict__ xl)
{
    int idx = blockIdx.x * blockDim.x + threadIdx.x;   // B*T*D/2
    int d2 = idx & 511;
    int bt = idx >> 9;
    float2 v = *reinterpret_cast<const float2*>(emb + (size_t)ids[bt] * D_SZ + d2 * 2);
    *reinterpret_cast<float2*>(x + (size_t)bt * D_SZ + d2 * 2) = v;
    u32 h, l;
    split2(v.x, v.y, h, l);
    xh[idx] = h; xl[idx] = l;
}

__global__ void dirichlet_kernel(float* __restrict__ g)
{
    int d = blockIdx.x * blockDim.x + threadIdx.x;
    if (d >= T_SZ) return;
    double s = 0.0;
    for (int k = 1; k < KEEP; k++)
        s += cos(2.0 * PI_D * (double)k * (double)d / (double)T_SZ);
    g[d] = (float)((1.0 + 2.0 * s) / (double)T_SZ);
}

__global__ void buildG_kernel(const float* __restrict__ g, float* __restrict__ G)
{
    int i = blockIdx.x * blockDim.x + threadIdx.x;
    int t = i >> 10, s = i & (T_SZ - 1);
    G[i] = g[(t - s) & (T_SZ - 1)];
}

__global__ __launch_bounds__(256) void rho_kernel(const float* __restrict__ hlp,
                                                  const float* __restrict__ x,
                                                  float* __restrict__ rho)
{
    size_t row = (size_t)blockIdx.x * D_SZ;
    int tid = threadIdx.x;
    float s1 = 0.f, s2 = 0.f;
#pragma unroll
    for (int i = 0; i < 4; i++) {
        float a = hlp[row + tid + i * 256];
        float b = x  [row + tid + i * 256];
        s1 += a * a; s2 += b * b;
    }
    for (int o = 16; o > 0; o >>= 1) {
        s1 += __shfl_xor_sync(0xffffffffu, s1, o);
        s2 += __shfl_xor_sync(0xffffffffu, s2, o);
    }
    __shared__ float r1[8], r2[8];
    if ((tid & 31) == 0) { r1[tid >> 5] = s1; r2[tid >> 5] = s2; }
    __syncthreads();
    if (tid == 0) {
        float t1 = 0.f, t2 = 0.f;
        for (int i = 0; i < 8; i++) { t1 += r1[i]; t2 += r2[i]; }
        rho[blockIdx.x] = t1 / (t2 + EPSF);
    }
}

__global__ void select_blocks(const float* __restrict__ rho, int* __restrict__ sel)
{
    __shared__ float bq[B_SZ][M_BLK];
    int tid = threadIdx.x;
    if (tid < B_SZ * M_BLK) {
        int b = tid >> 5, m = tid & 31;
        float s = 0.f;
        for (int i = 0; i < BS_SZ; i++) s += rho[b * T_SZ + m * BS_SZ + i];
        bq[b][m] = s * (1.f / BS_SZ);
        sel[tid] = 0;
    }
    __syncthreads();
    if (tid < B_SZ) {
        int b = tid;
        bool picked[M_BLK];
        for (int m = 0; m < M_BLK; m++) picked[m] = false;
        for (int it = 0; it < TOPK; it++) {
            int best = -1; float bv = -3.4e38f;
            for (int m = 0; m < M_BLK; m++)
                if (!picked[m] && bq[b][m] > bv) { bv = bq[b][m]; best = m; }
            picked[best] = true;
            sel[b * M_BLK + best] = 1;
        }
    }
}

__global__ __launch_bounds__(256) void rmsnorm_split_kernel(
    const float* __restrict__ x, const float* __restrict__ w,
    u32* __restrict__ yh, u32* __restrict__ yl)
{
    size_t row = (size_t)blockIdx.x * D_SZ;
    int tid = threadIdx.x;
    float4 v = reinterpret_cast<const float4*>(x + row)[tid];
    float s = v.x * v.x + v.y * v.y + v.z * v.z + v.w * v.w;
    for (int o = 16; o > 0; o >>= 1) s += __shfl_xor_sync(0xffffffffu, s, o);
    __shared__ float red[8];
    if ((tid & 31) == 0) red[tid >> 5] = s;
    __syncthreads();
    float tot = 0.f;
    for (int i = 0; i < 8; i++) tot += red[i];
    float r = rsqrtf(tot * (1.f / D_SZ) + EPSF);
    float4 wv = reinterpret_cast<const float4*>(w)[tid];
    u32 h0, l0, h1, l1;
    split2(v.x * r * wv.x, v.y * r * wv.y, h0, l0);
    split2(v.z * r * wv.z, v.w * r * wv.w, h1, l1);
    size_t c = row / 2 + tid * 2;
    yh[c] = h0; yh[c + 1] = h1;
    yl[c] = l0; yl[c + 1] = l1;
}

__global__ void rope_split_kernel(const float* __restrict__ qkv,
                                  u32* __restrict__ qkvh, u32* __restrict__ qkvl)
{
    const int QK = B_SZ * T_SZ * D_SZ;
    int idx = blockIdx.x * blockDim.x + threadIdx.x;   // B*T*H*16
    int j2 = idx & 15;
    int h  = (idx >> 4) & (H_SZ - 1);
    int t  = (idx >> 8) & (T_SZ - 1);
    int b  = idx >> 18;
    int e0 = 2 * j2;
    float inv0 = (float)(1.0 / pow(10000.0, (double)(2 * e0)     / (double)DH_SZ));
    float inv1 = (float)(1.0 / pow(10000.0, (double)(2 * (e0+1)) / (double)DH_SZ));
    float c0 = cosf(t * inv0), s0 = sinf(t * inv0);
    float c1 = cosf(t * inv1), s1 = sinf(t * inv1);
    size_t base = ((size_t)(b * T_SZ + t)) * D_SZ + h * DH_SZ + e0;
    float2 qa = *reinterpret_cast<const float2*>(qkv + base);
    float2 qb = *reinterpret_cast<const float2*>(qkv + base + 32);
    float2 ka = *reinterpret_cast<const float2*>(qkv + QK + base);
    float2 kb = *reinterpret_cast<const float2*>(qkv + QK + base + 32);
    float q0 = qa.x * c0 - qb.x * s0, q1 = qa.y * c1 - qb.y * s1;
    float q2 = qb.x * c0 + qa.x * s0, q3 = qb.y * c1 + qa.y * s1;
    float k0 = ka.x * c0 - kb.x * s0, k1 = ka.y * c1 - kb.y * s1;
    float k2 = kb.x * c0 + ka.x * s0, k3 = kb.y * c1 + ka.y * s1;
    size_t p0 = base >> 1, p1 = (base + 32) >> 1;
    const size_t QK2 = QK / 2;
    u32 hh_, ll_;
    split2(q0, q1, hh_, ll_); qkvh[p0] = hh_;       qkvl[p0] = ll_;
    split2(q2, q3, hh_, ll_); qkvh[p1] = hh_;       qkvl[p1] = ll_;
    split2(k0, k1, hh_, ll_); qkvh[QK2 + p0] = hh_; qkvl[QK2 + p0] = ll_;
    split2(k2, k3, hh_, ll_); qkvh[QK2 + p1] = hh_; qkvl[QK2 + p1] = ll_;
}

__global__ __launch_bounds__(256) void masked_softmax_split_kernel(
    const float* __restrict__ s, const int* __restrict__ sel,
    u32* __restrict__ ph, u32* __restrict__ pl)
{
    int gid = blockIdx.x;
    int tq = gid & (T_SZ - 1);
    int b  = gid / (H_SZ * T_SZ);
    size_t row = (size_t)gid * T_SZ;
    int tid = threadIdx.x;
    const float scale = 0.125f;
    int qblk  = tq >> 5;
    int qbmin = (tq >> 7) << 2;
    int qbmax = qbmin + 3;

    float v[4];
    bool wlive[2];
    float mx = -3.4e38f;
#pragma unroll
    for (int i = 0; i < 2; i++) {
        int p  = tid + i * 256;
        int kb = p >> 4;
        bool blive = (kb <= qblk) && (sel[b * M_BLK + kb] || kb == qblk);
        wlive[i]   = (kb <= qbmax) && (sel[b * M_BLK + kb] || kb >= qbmin);
        float2 vv = make_float2(-1e9f, -1e9f);
        if (blive) vv = *reinterpret_cast<const float2*>(s + row + 2 * p);
        int e0 = 2 * p;
        v[2*i]   = (blive && e0     <= tq) ? vv.x * scale : -1e9f;
        v[2*i+1] = (blive && e0 + 1 <= tq) ? vv.y * scale : -1e9f;
        mx = fmaxf(mx, fmaxf(v[2*i], v[2*i+1]));
    }
    for (int o = 16; o > 0; o >>= 1) mx = fmaxf(mx, __shfl_xor_sync(0xffffffffu, mx, o));
    __shared__ float red[8];
    if ((tid & 31) == 0) red[tid >> 5] = mx;
    __syncthreads();
    float m = red[0];
    for (int i = 1; i < 8; i++) m = fmaxf(m, red[i]);
    __syncthreads();
    float sum = 0.f;
#pragma unroll
    for (int i = 0; i < 4; i++) { v[i] = expf(v[i] - m); sum += v[i]; }
    for (int o = 16; o > 0; o >>= 1) sum += __shfl_xor_sync(0xffffffffu, sum, o);
    if ((tid & 31) == 0) red[tid >> 5] = sum;
    __syncthreads();
    float tot = 0.f;
    for (int i = 0; i < 8; i++) tot += red[i];
    float inv = 1.f / tot;
    size_t prow = row >> 1;
#pragma unroll
    for (int i = 0; i < 2; i++) {
        if (!wlive[i]) continue;
        int p = tid + i * 256;
        u32 hh_, ll_;
        split2(v[2*i] * inv, v[2*i+1] * inv, hh_, ll_);
        ph[prow + p] = hh_; pl[prow + p] = ll_;
    }
}

__global__ __launch_bounds__(256) void silu_split_kernel(const float* __restrict__ f13,
                                                         u32* __restrict__ gh, u32* __restrict__ gl,
                                                         long n2)
{
    long idx = (long)blockIdx.x * blockDim.x + threadIdx.x;
    if (idx >= n2) return;
    const long F3OFF = (long)B_SZ * T_SZ * FF_SZ / 2;
    float2 a = reinterpret_cast<const float2*>(f13)[idx];
    float2 g = reinterpret_cast<const float2*>(f13)[F3OFF + idx];
    float y0 = a.x / (1.f + expf(-a.x)) * g.x;
    float y1 = a.y / (1.f + expf(-a.y)) * g.y;
    u32 h, l;
    split2(y0, y1, h, l);
    gh[idx] = h; gl[idx] = l;
}

// ---------------- host launchers ----------------
static const int SMEM_KN64 = NSTG * (2*128*LDA_S + 2*32*(64+8)) * 2;
static const int SMEM_NK64 = NSTG * (2*128*LDA_S + 2*64*LDA_S)  * 2;

static void gemm_kn(const u16* Ah, const u16* Al, const u16* Bh, const u16* Bl, float* C,
                    int M, int N, int K, int lda, int ldb, int ldc,
                    long sAb, long sBb, long sCb, long sAh, long sBh, long sCh,
                    int Hdim, int nb, int beta,
                    const int* sel = 0, int smode = 0, u16* Ch = 0, u16* Cl = 0)
{
    dim3 grid(N / 64, M / 128, nb);
    bf16_gemm_kernel<false><<<grid, 256, SMEM_KN64>>>(
        Ah, Al, Bh, Bl, C, K, lda, ldb, ldc, sAb, sBb, sCb, sAh, sBh, sCh, Hdim, beta,
        sel, smode, (u32*)Ch, (u32*)Cl);
}

static void gemm_nk(const u16* Ah, const u16* Al, const u16* Bh, const u16* Bl, float* C,
                    int M, int N, int K, int lda, int ldb, int ldc,
                    long sAb, long sBb, long sCb, long sAh, long sBh, long sCh,
                    int Hdim, int nb, int beta, const int* sel, int smode)
{
    dim3 grid(N / 64, M / 128, nb);
    bf16_gemm_kernel<true><<<grid, 256, SMEM_NK64>>>(
        Ah, Al, Bh, Bl, C, K, lda, ldb, ldc, sAb, sBb, sCb, sAh, sBh, sCh, Hdim, beta,
        sel, smode, (u32*)0, (u32*)0);
}

static void split_s(cudaStream_t st, const float* in, u16* hi, u16* lo, long n)
{
    long n4 = n / 4;
    split_kernel<<<(unsigned)((n4 + 255) / 256), 256, 0, st>>>(
        in, (uint2*)hi, (uint2*)lo, n4);
}

extern "C" void kernel_launch(void* const* d_in, const int* in_sizes, int n_in,
                              void* d_out, int out_size)
{
    const int*   ids        = (const int*)  d_in[0];
    const float* emb        = (const float*)d_in[1];
    const float* wq         = (const float*)d_in[2];
    const float* wk         = (const float*)d_in[3];
    const float* wv         = (const float*)d_in[4];
    const float* wo         = (const float*)d_in[5];
    const float* w1         = (const float*)d_in[6];
    const float* w2         = (const float*)d_in[7];
    const float* w3         = (const float*)d_in[8];
    const float* attn_norm  = (const float*)d_in[9];
    const float* ffn_norm   = (const float*)d_in[10];
    const float* final_norm = (const float*)d_in[11];
    const float* lm_head    = (const float*)d_in[12];
    float* out = (float*)d_out;

    static bool attrs_set = false;
    static cudaStream_t s1 = 0;
    static cudaEvent_t evFork = 0, evJoin = 0;
    if (!attrs_set) {
        cudaFuncSetAttribute(bf16_gemm_kernel<false>,
                             cudaFuncAttributeMaxDynamicSharedMemorySize, SMEM_KN64);
        cudaFuncSetAttribute(bf16_gemm_kernel<true>,
                             cudaFuncAttributeMaxDynamicSharedMemorySize, SMEM_NK64);
        cudaStreamCreateWithFlags(&s1, cudaStreamNonBlocking);
        cudaEventCreateWithFlags(&evFork, cudaEventDisableTiming);
        cudaEventCreateWithFlags(&evJoin, cudaEventDisableTiming);
        attrs_set = true;
    }

    float *x, *h, *qkv, *o, *sc, *f13, *G, *gk, *rho;
    int* sel;
    cudaGetSymbolAddress((void**)&x,   d_x);
    cudaGetSymbolAddress((void**)&h,   d_h);
    cudaGetSymbolAddress((void**)&qkv, d_qkv);
    cudaGetSymbolAddress((void**)&o,   d_o);
    cudaGetSymbolAddress((void**)&sc,  d_sc);
    cudaGetSymbolAddress((void**)&f13, d_f13);
    cudaGetSymbolAddress((void**)&G,   d_G);
    cudaGetSymbolAddress((void**)&gk,  d_gk);
    cudaGetSymbolAddress((void**)&rho, d_rho);
    cudaGetSymbolAddress((void**)&sel, d_sel);

    u16 *xh,*xl,*Gh,*Gl,*hh,*hl,*qkvh,*qkvl,*sch,*scl,*oh,*ol,*f1h,*f1l;
    u16 *wqkvh,*wqkvl,*woh,*wol,*w13h,*w13l,*w2h,*w2l,*lmh,*lml;
    cudaGetSymbolAddress((void**)&xh, d_xh);     cudaGetSymbolAddress((void**)&xl, d_xl);
    cudaGetSymbolAddress((void**)&Gh, d_Gh);     cudaGetSymbolAddress((void**)&Gl, d_Gl);
    cudaGetSymbolAddress((void**)&hh, d_hh);     cudaGetSymbolAddress((void**)&hl, d_hl);
    cudaGetSymbolAddress((void**)&qkvh, d_qkvh); cudaGetSymbolAddress((void**)&qkvl, d_qkvl);
    cudaGetSymbolAddress((void**)&sch, d_sch);   cudaGetSymbolAddress((void**)&scl, d_scl);
    cudaGetSymbolAddress((void**)&oh, d_oh);     cudaGetSymbolAddress((void**)&ol, d_ol);
    cudaGetSymbolAddress((void**)&f1h, d_f1h);   cudaGetSymbolAddress((void**)&f1l, d_f1l);
    cudaGetSymbolAddress((void**)&wqkvh, d_wqkvh); cudaGetSymbolAddress((void**)&wqkvl, d_wqkvl);
    cudaGetSymbolAddress((void**)&woh, d_woh);   cudaGetSymbolAddress((void**)&wol, d_wol);
    cudaGetSymbolAddress((void**)&w13h, d_w13h); cudaGetSymbolAddress((void**)&w13l, d_w13l);
    cudaGetSymbolAddress((void**)&w2h, d_w2h);   cudaGetSymbolAddress((void**)&w2l, d_w2l);
    cudaGetSymbolAddress((void**)&lmh, d_lmh);   cudaGetSymbolAddress((void**)&lml, d_lml);

    const int  BT = B_SZ * T_SZ;
    const long DD = (long)D_SZ * D_SZ;
    const long DF = (long)D_SZ * FF_SZ;
    const long QK = (long)BT * D_SZ;

    // ---- fork: weight splits on s1, overlapping the low-pass chain on s0 ----
    cudaEventRecord(evFork, 0);
    cudaStreamWaitEvent(s1, evFork, 0);
    for (int l = 0; l < L_SZ; l++) {
        split_s(s1, wq + l * DD, wqkvh + (3 * l + 0) * DD, wqkvl + (3 * l + 0) * DD, DD);
        split_s(s1, wk + l * DD, wqkvh + (3 * l + 1) * DD, wqkvl + (3 * l + 1) * DD, DD);
        split_s(s1, wv + l * DD, wqkvh + (3 * l + 2) * DD, wqkvl + (3 * l + 2) * DD, DD);
        split_s(s1, w1 + l * DF, w13h + (2 * l + 0) * DF, w13l + (2 * l + 0) * DF, DF);
        split_s(s1, w3 + l * DF, w13h + (2 * l + 1) * DF, w13l + (2 * l + 1) * DF, DF);
    }
    split_s(s1, wo, woh, wol, (long)L_SZ * DD);
    split_s(s1, w2, w2h, w2l, (long)L_SZ * DF);
    split_s(s1, lm_head, lmh, lml, (long)D_SZ * V_SZ);
    cudaEventRecord(evJoin, s1);

    // ---- main stream: embedding + low-pass quality -> block selection ----
    embed_split_kernel<<<(B_SZ * T_SZ * D_SZ / 2) / 256, 256>>>(
        ids, emb, x, (u32*)xh, (u32*)xl);
    dirichlet_kernel<<<T_SZ / 256, 256>>>(gk);
    buildG_kernel<<<(T_SZ * T_SZ) / 256, 256>>>(gk, G);
    split_s(0, G, Gh, Gl, (long)T_SZ * T_SZ);
    gemm_kn(Gh, Gl, xh, xl, h, T_SZ, D_SZ, T_SZ, T_SZ, D_SZ, D_SZ,
            0, (long)T_SZ * D_SZ, (long)T_SZ * D_SZ, 0, 0, 0, 1, B_SZ, 0);
    rho_kernel<<<BT, 256>>>(h, x, rho);
    select_blocks<<<1, 64>>>(rho, sel);

    // ---- join: weight planes must be ready before the layer loop ----
    cudaStreamWaitEvent(0, evJoin, 0);

    // 3) transformer layers
    for (int l = 0; l < L_SZ; l++) {
        rmsnorm_split_kernel<<<BT, 256>>>(x, attn_norm + (size_t)l * D_SZ, (u32*)hh, (u32*)hl);

        // fused QKV (z in {0,1,2})
        gemm_kn(hh, hl, wqkvh + 3 * l * DD, wqkvl + 3 * l * DD, qkv,
                BT, D_SZ, D_SZ, D_SZ, D_SZ, D_SZ,
                0, 0, 0, 0, DD, QK, 3, 3, 0, 0, 0,
                (u16*)qkvh, (u16*)qkvl);

        rope_split_kernel<<<(B_SZ * T_SZ * H_SZ * 16) / 256, 256>>>(
            qkv, (u32*)qkvh, (u32*)qkvl);

        gemm_nk(qkvh, qkvl, qkvh + QK, qkvl + QK, sc, T_SZ, T_SZ, DH_SZ,
                D_SZ, D_SZ, T_SZ,
                (long)T_SZ * D_SZ, (long)T_SZ * D_SZ, (long)H_SZ * T_SZ * T_SZ,
                DH_SZ, DH_SZ, (long)T_SZ * T_SZ, H_SZ, B_SZ * H_SZ, 0, sel, 1);

        masked_softmax_split_kernel<<<B_SZ * H_SZ * T_SZ, 256>>>(
            sc, sel, (u32*)sch, (u32*)scl);

        gemm_kn(sch, scl, qkvh + 2 * QK, qkvl + 2 * QK, o, T_SZ, DH_SZ, T_SZ,
                T_SZ, D_SZ, D_SZ,
                (long)H_SZ * T_SZ * T_SZ, (long)T_SZ * D_SZ, (long)T_SZ * D_SZ,
                (long)T_SZ * T_SZ, DH_SZ, DH_SZ, H_SZ, B_SZ * H_SZ, 0, sel, 2, oh, ol);

        gemm_kn(oh, ol, woh + l * DD, wol + l * DD, x, BT, D_SZ, D_SZ, D_SZ, D_SZ, D_SZ,
                0, 0, 0, 0, 0, 0, 1, 1, 1);

        // FFN: fused w1/w3 (z in {0,1})
        rmsnorm_split_kernel<<<BT, 256>>>(x, ffn_norm + (size_t)l * D_SZ, (u32*)hh, (u32*)hl);
        gemm_kn(hh, hl, w13h + 2 * l * DF, w13l + 2 * l * DF, f13,
                BT, FF_SZ, D_SZ, D_SZ, FF_SZ, FF_SZ,
                0, 0, 0, 0, DF, (long)BT * FF_SZ, 2, 2, 0);
        silu_split_kernel<<<(BT * FF_SZ / 2 + 255) / 256, 256>>>(
            f13, (u32*)f1h, (u32*)f1l, (long)BT * FF_SZ / 2);
        gemm_kn(f1h, f1l, w2h + l * DF, w2l + l * DF, x, BT, D_SZ, FF_SZ, FF_SZ, D_SZ, D_SZ,
                0, 0, 0, 0, 0, 0, 1, 1, 1);
    }

    // 4) final norm + lm_head
    rmsnorm_split_kernel<<<BT, 256>>>(x, final_norm, (u32*)hh, (u32*)hl);
    gemm_kn(hh, hl, lmh, lml, out, BT, V_SZ, D_SZ, D_SZ, V_SZ, V_SZ,
            0, 0, 0, 0, 0, 0, 1, 1, 0);
}

// round 16
// speedup vs baseline: 1.1256x; 1.0566x over previous
#include <cuda_runtime.h>
#include <math.h>

typedef unsigned short u16;
typedef unsigned int   u32;

// ---------------- problem constants ----------------
#define B_SZ 2
#define T_SZ 1024
#define D_SZ 1024
#define H_SZ 16
#define DH_SZ 64
#define FF_SZ 4096
#define L_SZ 2
#define V_SZ 32000
#define M_BLK 32
#define BS_SZ 32
#define TOPK 8
#define KEEP 128
#define EPSF 1e-6f
#define PI_D 3.14159265358979323846

// ---------------- fp32 scratch ----------------
__device__ float d_x  [B_SZ*T_SZ*D_SZ];
__device__ float d_h  [B_SZ*T_SZ*D_SZ];
__device__ float d_qkv[3*B_SZ*T_SZ*D_SZ];            // contiguous q|k|v
__device__ float d_o  [B_SZ*T_SZ*D_SZ];
__device__ float d_sc [(size_t)B_SZ*H_SZ*T_SZ*T_SZ];
__device__ float d_f13[2*B_SZ*T_SZ*FF_SZ];           // contiguous f1|f3
__device__ float d_G  [T_SZ*T_SZ];
__device__ float d_gk [T_SZ];
__device__ float d_rho[B_SZ*T_SZ];
__device__ int   d_sel[B_SZ*M_BLK];

// ---------------- bf16 hi/lo planes ----------------
__device__ u16 d_xh  [B_SZ*T_SZ*D_SZ],   d_xl  [B_SZ*T_SZ*D_SZ];
__device__ u16 d_Gh  [T_SZ*T_SZ],        d_Gl  [T_SZ*T_SZ];
__device__ u16 d_hh  [B_SZ*T_SZ*D_SZ],   d_hl  [B_SZ*T_SZ*D_SZ];
__device__ u16 d_qkvh[3*B_SZ*T_SZ*D_SZ], d_qkvl[3*B_SZ*T_SZ*D_SZ];
__device__ u16 d_sch [(size_t)B_SZ*H_SZ*T_SZ*T_SZ], d_scl[(size_t)B_SZ*H_SZ*T_SZ*T_SZ];
__device__ u16 d_oh  [B_SZ*T_SZ*D_SZ],   d_ol  [B_SZ*T_SZ*D_SZ];
__device__ u16 d_f1h [B_SZ*T_SZ*FF_SZ],  d_f1l [B_SZ*T_SZ*FF_SZ];
// weights (natural [K][N] layout planes)
__device__ u16 d_wqkvh[L_SZ*3*D_SZ*D_SZ], d_wqkvl[L_SZ*3*D_SZ*D_SZ];
__device__ u16 d_woh [L_SZ*D_SZ*D_SZ],   d_wol [L_SZ*D_SZ*D_SZ];
__device__ u16 d_w13h[L_SZ*2*D_SZ*FF_SZ], d_w13l[L_SZ*2*D_SZ*FF_SZ];
__device__ u16 d_w2h [L_SZ*FF_SZ*D_SZ],  d_w2l [L_SZ*FF_SZ*D_SZ];
__device__ u16 d_lmh [(size_t)D_SZ*V_SZ], d_lml [(size_t)D_SZ*V_SZ];

// ---------------- split helpers ----------------
__device__ __forceinline__ void split2(float v0, float v1, u32 &hi, u32 &lo)
{
    asm("cvt.rn.bf16x2.f32 %0, %1, %2;" : "=r"(hi) : "f"(v1), "f"(v0));
    float h0 = __int_as_float(hi << 16);
    float h1 = __int_as_float(hi & 0xffff0000u);
    asm("cvt.rn.bf16x2.f32 %0, %1, %2;" : "=r"(lo) : "f"(v1 - h1), "f"(v0 - h0));
}

__global__ __launch_bounds__(256) void split_kernel(const float* __restrict__ in,
                                                    uint2* __restrict__ hi, uint2* __restrict__ lo,
                                                    long n4)
{
    long idx = (long)blockIdx.x * blockDim.x + threadIdx.x;
    if (idx >= n4) return;
    float4 v = reinterpret_cast<const float4*>(in)[idx];
    u32 h0, l0, h1, l1;
    split2(v.x, v.y, h0, l0);
    split2(v.z, v.w, h1, l1);
    hi[idx] = make_uint2(h0, h1);
    lo[idx] = make_uint2(l0, l1);
}

#define MMA_BF16(ACC, A, B0, B1)                                                 \
    asm volatile(                                                                \
        "mma.sync.aligned.m16n8k16.row.col.f32.bf16.bf16.f32 "                   \
        "{%0,%1,%2,%3}, {%4,%5,%6,%7}, {%8,%9}, {%0,%1,%2,%3};"                  \
        : "+f"(ACC[0]), "+f"(ACC[1]), "+f"(ACC[2]), "+f"(ACC[3])                 \
        : "r"(A[0]), "r"(A[1]), "r"(A[2]), "r"(A[3]), "r"(B0), "r"(B1))

#define LDSM4(R, ADDR)                                                           \
    asm volatile("ldmatrix.sync.aligned.m8n8.x4.shared.b16 {%0,%1,%2,%3},[%4];"  \
        : "=r"(R[0]), "=r"(R[1]), "=r"(R[2]), "=r"(R[3]) : "r"(ADDR))

#define LDSM4T(R0, R1, R2, R3, ADDR)                                             \
    asm volatile("ldmatrix.sync.aligned.m8n8.x4.trans.shared.b16 {%0,%1,%2,%3},[%4];" \
        : "=r"(R0), "=r"(R1), "=r"(R2), "=r"(R3) : "r"(ADDR))

// =====================================================================
// bf16 hi/lo 3-term GEMM, 3-stage cp.async pipeline, block-sparse modes.
// smode 0: dense. smode 1: scores (skip dead output tiles).
// smode 2: attn@V (iterate only live 32-wide K blocks).
// Optional Chp/Clp: epilogue also emits bf16 hi/lo planes (beta=0 only).
// BNK=true: B stored row-major [N][K].
// =====================================================================
#define LDA_S 40   // u16 stride (80B)
#define NSTG 3

template<bool BNK>
__global__ __launch_bounds__(256, 2)
void bf16_gemm_kernel(const u16* __restrict__ Ahi, const u16* __restrict__ Alo,
                      const u16* __restrict__ Bhi, const u16* __restrict__ Blo,
                      float* __restrict__ Cg,
                      int K, int lda, int ldb, int ldc,
                      long sAb, long sBb, long sCb, long sAh, long sBh, long sCh,
                      int Hdim, int beta,
                      const int* __restrict__ selp, int smode,
                      u32* __restrict__ Chp, u32* __restrict__ Clp)
{
    constexpr int BM = 128, BK = 32, BN = 64, WM = 4, WN = 2;
    constexpr int AM = 2, AN = 4;
    constexpr int LDB_S = BNK ? LDA_S : (BN + 8);
    constexpr int A_PL  = BM * LDA_S;
    constexpr int B_PL  = BNK ? (BN * LDA_S) : (BK * LDB_S);
    constexpr int STAGE = 2 * A_PL + 2 * B_PL;

    extern __shared__ u16 smu[];
    __shared__ int klist[129];
    __shared__ int kcnt;

    int z = blockIdx.z, zb = z / Hdim, zh = z % Hdim;
    const int tid = threadIdx.x, lane = tid & 31, w = tid >> 5;
    const int row0 = blockIdx.y * BM, col0 = blockIdx.x * BN;

    if (smode == 1) {
        int qbmin = row0 >> 5, qbmax = qbmin + 3;
        bool need = false;
#pragma unroll
        for (int i = 0; i < 2; i++) {
            int kb = (col0 >> 5) + i;
            if (kb <= qbmax && (selp[zb * M_BLK + kb] || kb >= qbmin)) need = true;
        }
        if (!need) return;
    }
    if (tid == 0) {
        int c = 0;
        if (smode == 2) {
            int qbmin = row0 >> 5, qbmax = qbmin + 3;
            for (int kb = 0; kb < K / 32; kb++)
                if (kb <= qbmax && (selp[zb * M_BLK + kb] || kb >= qbmin))
                    klist[c++] = kb * 32;
        } else {
            for (int t = 0; t < K / BK; t++) klist[c++] = t * BK;
        }
        kcnt = c;
    }
    __syncthreads();
    const int ntiles = kcnt;

    const u16* Ah = Ahi + zb * sAb + zh * sAh;
    const u16* Al = Alo + zb * sAb + zh * sAh;
    const u16* Bh = Bhi + zb * sBb + zh * sBh;
    const u16* Bl = Blo + zb * sBb + zh * sBh;
    float*     C  = Cg  + zb * sCb + zh * sCh;
    u32* Ch = Chp ? Chp + (zb * sCb + zh * sCh) / 2 : (u32*)0;
    u32* Cl = Clp ? Clp + (zb * sCb + zh * sCh) / 2 : (u32*)0;

    const int wm = w % WM, wn = w / WM;
    const int mW = wm * (BM / WM), nW = wn * (BN / WN);

    float acc[AM][AN][4];
#pragma unroll
    for (int i = 0; i < AM; i++)
#pragma unroll
        for (int j = 0; j < AN; j++)
#pragma unroll
            for (int r = 0; r < 4; r++) acc[i][j][r] = 0.f;

    auto cpa = [&](u16* dst, const u16* src) {
        u32 d = (u32)__cvta_generic_to_shared(dst);
        asm volatile("cp.async.cg.shared.global [%0],[%1],16;\n" :: "r"(d), "l"(src));
    };
    auto load_tile = [&](int s, int kt) {
        u16* base = smu + s * STAGE;
#pragma unroll
        for (int i = 0; i < 2; i++) {
            int ch = tid + i * 256;
            int r = ch >> 2, c = ch & 3;
            size_t go = (size_t)(row0 + r) * lda + kt + c * 8;
            cpa(base + r * LDA_S + c * 8,        Ah + go);
            cpa(base + A_PL + r * LDA_S + c * 8, Al + go);
        }
        u16* bb = base + 2 * A_PL;
        if (BNK) {
            int r = tid >> 2, c = tid & 3;
            size_t go = (size_t)(col0 + r) * ldb + kt + c * 8;
            cpa(bb + r * LDA_S + c * 8,        Bh + go);
            cpa(bb + B_PL + r * LDA_S + c * 8, Bl + go);
        } else {
            int r = tid >> 3, c = tid & 7;
            size_t go = (size_t)(kt + r) * ldb + col0 + c * 8;
            cpa(bb + r * LDB_S + c * 8,        Bh + go);
            cpa(bb + B_PL + r * LDB_S + c * 8, Bl + go);
        }
    };

    // 3-stage pipeline: up to 2 tiles in flight while computing one.
    load_tile(0, klist[0]);
    asm volatile("cp.async.commit_group;\n" ::: "memory");
    if (ntiles > 1) {
        load_tile(1, klist[1]);
        asm volatile("cp.async.commit_group;\n" ::: "memory");
    }

    for (int t = 0; t < ntiles; t++) {
        int s = t % NSTG;
        if (t + 1 < ntiles) {
            asm volatile("cp.async.wait_group 1;\n" ::: "memory");
        } else {
            asm volatile("cp.async.wait_group 0;\n" ::: "memory");
        }
        __syncthreads();
        if (t + 2 < ntiles) {
            load_tile((t + 2) % NSTG, klist[t + 2]);
            asm volatile("cp.async.commit_group;\n" ::: "memory");
        }

        const u16* sa = smu + s * STAGE;
        const u16* sb = sa + 2 * A_PL;
#pragma unroll
        for (int ks = 0; ks < 2; ks++) {
            u32 ah[AM][4], al[AM][4], bh[AN][2], bl[AN][2];
            int arow = ((lane >> 3) & 1) * 8 + (lane & 7);
            int acol = ks * 16 + (lane >> 4) * 8;
#pragma unroll
            for (int am = 0; am < AM; am++) {
                const u16* p = sa + (mW + am * 16 + arow) * LDA_S + acol;
                u32 addr = (u32)__cvta_generic_to_shared(p);
                LDSM4(ah[am], addr);
                LDSM4(al[am], addr + A_PL * 2);
            }
            if (BNK) {
                int brow = ((lane >> 4) & 1) * 8 + (lane & 7);
                int bcol = ks * 16 + ((lane >> 3) & 1) * 8;
#pragma unroll
                for (int a2 = 0; a2 < AN / 2; a2++) {
                    const u16* p = sb + (nW + a2 * 16 + brow) * LDA_S + bcol;
                    u32 addr = (u32)__cvta_generic_to_shared(p);
                    asm volatile("ldmatrix.sync.aligned.m8n8.x4.shared.b16 {%0,%1,%2,%3},[%4];"
                        : "=r"(bh[2*a2][0]), "=r"(bh[2*a2][1]),
                          "=r"(bh[2*a2+1][0]), "=r"(bh[2*a2+1][1]) : "r"(addr));
                    asm volatile("ldmatrix.sync.aligned.m8n8.x4.shared.b16 {%0,%1,%2,%3},[%4];"
                        : "=r"(bl[2*a2][0]), "=r"(bl[2*a2][1]),
                          "=r"(bl[2*a2+1][0]), "=r"(bl[2*a2+1][1]) : "r"(addr + B_PL * 2));
                }
            } else {
                int brow = ks * 16 + ((lane >> 3) & 1) * 8 + (lane & 7);
                int bcol = (lane >> 4) * 8;
#pragma unroll
                for (int a2 = 0; a2 < AN / 2; a2++) {
                    const u16* p = sb + brow * LDB_S + nW + a2 * 16 + bcol;
                    u32 addr = (u32)__cvta_generic_to_shared(p);
                    LDSM4T(bh[2*a2][0], bh[2*a2][1], bh[2*a2+1][0], bh[2*a2+1][1], addr);
                    LDSM4T(bl[2*a2][0], bl[2*a2][1], bl[2*a2+1][0], bl[2*a2+1][1],
                           addr + B_PL * 2);
                }
            }
#pragma unroll
            for (int am = 0; am < AM; am++)
#pragma unroll
                for (int an = 0; an < AN; an++) {
                    MMA_BF16(acc[am][an], ah[am], bh[an][0], bh[an][1]);
                    MMA_BF16(acc[am][an], ah[am], bl[an][0], bl[an][1]);
                    MMA_BF16(acc[am][an], al[am], bh[an][0], bh[an][1]);
                }
        }
        __syncthreads();
    }

#pragma unroll
    for (int am = 0; am < AM; am++)
#pragma unroll
        for (int an = 0; an < AN; an++) {
            int r = row0 + mW + am * 16 + (lane >> 2);
            int c = col0 + nW + an * 8 + (lane & 3) * 2;
            size_t i0 = (size_t)r * ldc + c;
            size_t i1 = (size_t)(r + 8) * ldc + c;
            float2 v0 = make_float2(acc[am][an][0], acc[am][an][1]);
            float2 v1 = make_float2(acc[am][an][2], acc[am][an][3]);
            if (beta) {
                float2 p0 = *reinterpret_cast<const float2*>(C + i0);
                float2 p1 = *reinterpret_cast<const float2*>(C + i1);
                v0.x += p0.x; v0.y += p0.y; v1.x += p1.x; v1.y += p1.y;
            }
            *reinterpret_cast<float2*>(C + i0) = v0;
            *reinterpret_cast<float2*>(C + i1) = v1;
            if (Ch) {
                u32 hh_, ll_;
                split2(v0.x, v0.y, hh_, ll_);
                Ch[i0 >> 1] = hh_; Cl[i0 >> 1] = ll_;
                split2(v1.x, v1.y, hh_, ll_);
                Ch[i1 >> 1] = hh_; Cl[i1 >> 1] = ll_;
            }
        }
}

// ---------------- elementwise kernels ----------------
__global__ void embed_split_kernel(const int* __restrict__ ids, const float* __restrict__ emb,
                                   float* __restrict__ x, u32* __restrict__ xh, u32* __restrict__ xl)
{
    int idx = blockIdx.x * blockDim.x + threadIdx.x;   // B*T*D/2
    int d2 = idx & 511;
    int bt = idx >> 9;
    float2 v = *reinterpret_cast<const float2*>(emb + (size_t)ids[bt] * D_SZ + d2 * 2);
    *reinterpret_cast<float2*>(x + (size_t)bt * D_SZ + d2 * 2) = v;
    u32 h, l;
    split2(v.x, v.y, h, l);
    xh[idx] = h; xl[idx] = l;
}

__global__ void dirichlet_kernel(float* __restrict__ g)
{
    int d = blockIdx.x * blockDim.x + threadIdx.x;
    if (d >= T_SZ) return;
    double s = 0.0;
    for (int k = 1; k < KEEP; k++)
        s += cos(2.0 * PI_D * (double)k * (double)d / (double)T_SZ);
    g[d] = (float)((1.0 + 2.0 * s) / (double)T_SZ);
}

__global__ void buildG_kernel(const float* __restrict__ g, float* __restrict__ G)
{
    int i = blockIdx.x * blockDim.x + threadIdx.x;
    int t = i >> 10, s = i & (T_SZ - 1);
    G[i] = g[(t - s) & (T_SZ - 1)];
}

__global__ __launch_bounds__(256) void rho_kernel(const float* __restrict__ hlp,
                                                  const float* __restrict__ x,
                                                  float* __restrict__ rho)
{
    size_t row = (size_t)blockIdx.x * D_SZ;
    int tid = threadIdx.x;
    float s1 = 0.f, s2 = 0.f;
#pragma unroll
    for (int i = 0; i < 4; i++) {
        float a = hlp[row + tid + i * 256];
        float b = x  [row + tid + i * 256];
        s1 += a * a; s2 += b * b;
    }
    for (int o = 16; o > 0; o >>= 1) {
        s1 += __shfl_xor_sync(0xffffffffu, s1, o);
        s2 += __shfl_xor_sync(0xffffffffu, s2, o);
    }
    __shared__ float r1[8], r2[8];
    if ((tid & 31) == 0) { r1[tid >> 5] = s1; r2[tid >> 5] = s2; }
    __syncthreads();
    if (tid == 0) {
        float t1 = 0.f, t2 = 0.f;
        for (int i = 0; i < 8; i++) { t1 += r1[i]; t2 += r2[i]; }
        rho[blockIdx.x] = t1 / (t2 + EPSF);
    }
}

__global__ void select_blocks(const float* __restrict__ rho, int* __restrict__ sel)
{
    __shared__ float bq[B_SZ][M_BLK];
    int tid = threadIdx.x;
    if (tid < B_SZ * M_BLK) {
        int b = tid >> 5, m = tid & 31;
        float s = 0.f;
        for (int i = 0; i < BS_SZ; i++) s += rho[b * T_SZ + m * BS_SZ + i];
        bq[b][m] = s * (1.f / BS_SZ);
        sel[tid] = 0;
    }
    __syncthreads();
    if (tid < B_SZ) {
        int b = tid;
        bool picked[M_BLK];
        for (int m = 0; m < M_BLK; m++) picked[m] = false;
        for (int it = 0; it < TOPK; it++) {
            int best = -1; float bv = -3.4e38f;
            for (int m = 0; m < M_BLK; m++)
                if (!picked[m] && bq[b][m] > bv) { bv = bq[b][m]; best = m; }
            picked[best] = true;
            sel[b * M_BLK + best] = 1;
        }
    }
}

__global__ __launch_bounds__(256) void rmsnorm_split_kernel(
    const float* __restrict__ x, const float* __restrict__ w,
    u32* __restrict__ yh, u32* __restrict__ yl)
{
    size_t row = (size_t)blockIdx.x * D_SZ;
    int tid = threadIdx.x;
    float4 v = reinterpret_cast<const float4*>(x + row)[tid];
    float s = v.x * v.x + v.y * v.y + v.z * v.z + v.w * v.w;
    for (int o = 16; o > 0; o >>= 1) s += __shfl_xor_sync(0xffffffffu, s, o);
    __shared__ float red[8];
    if ((tid & 31) == 0) red[tid >> 5] = s;
    __syncthreads();
    float tot = 0.f;
    for (int i = 0; i < 8; i++) tot += red[i];
    float r = rsqrtf(tot * (1.f / D_SZ) + EPSF);
    float4 wv = reinterpret_cast<const float4*>(w)[tid];
    u32 h0, l0, h1, l1;
    split2(v.x * r * wv.x, v.y * r * wv.y, h0, l0);
    split2(v.z * r * wv.z, v.w * r * wv.w, h1, l1);
    size_t c = row / 2 + tid * 2;
    yh[c] = h0; yh[c + 1] = h1;
    yl[c] = l0; yl[c + 1] = l1;
}

__global__ void rope_split_kernel(const float* __restrict__ qkv,
                                  u32* __restrict__ qkvh, u32* __restrict__ qkvl)
{
    const int QK = B_SZ * T_SZ * D_SZ;
    int idx = blockIdx.x * blockDim.x + threadIdx.x;   // B*T*H*16
    int j2 = idx & 15;
    int h  = (idx >> 4) & (H_SZ - 1);
    int t  = (idx >> 8) & (T_SZ - 1);
    int b  = idx >> 18;
    int e0 = 2 * j2;
    float inv0 = (float)(1.0 / pow(10000.0, (double)(2 * e0)     / (double)DH_SZ));
    float inv1 = (float)(1.0 / pow(10000.0, (double)(2 * (e0+1)) / (double)DH_SZ));
    float c0 = cosf(t * inv0), s0 = sinf(t * inv0);
    float c1 = cosf(t * inv1), s1 = sinf(t * inv1);
    size_t base = ((size_t)(b * T_SZ + t)) * D_SZ + h * DH_SZ + e0;
    float2 qa = *reinterpret_cast<const float2*>(qkv + base);
    float2 qb = *reinterpret_cast<const float2*>(qkv + base + 32);
    float2 ka = *reinterpret_cast<const float2*>(qkv + QK + base);
    float2 kb = *reinterpret_cast<const float2*>(qkv + QK + base + 32);
    float q0 = qa.x * c0 - qb.x * s0, q1 = qa.y * c1 - qb.y * s1;
    float q2 = qb.x * c0 + qa.x * s0, q3 = qb.y * c1 + qa.y * s1;
    float k0 = ka.x * c0 - kb.x * s0, k1 = ka.y * c1 - kb.y * s1;
    float k2 = kb.x * c0 + ka.x * s0, k3 = kb.y * c1 + ka.y * s1;
    size_t p0 = base >> 1, p1 = (base + 32) >> 1;
    const size_t QK2 = QK / 2;
    u32 hh_, ll_;
    split2(q0, q1, hh_, ll_); qkvh[p0] = hh_;       qkvl[p0] = ll_;
    split2(q2, q3, hh_, ll_); qkvh[p1] = hh_;       qkvl[p1] = ll_;
    split2(k0, k1, hh_, ll_); qkvh[QK2 + p0] = hh_; qkvl[QK2 + p0] = ll_;
    split2(k2, k3, hh_, ll_); qkvh[QK2 + p1] = hh_; qkvl[QK2 + p1] = ll_;
}

__global__ __launch_bounds__(256) void masked_softmax_split_kernel(
    const float* __restrict__ s, const int* __restrict__ sel,
    u32* __restrict__ ph, u32* __restrict__ pl)
{
    int gid = blockIdx.x;
    int tq = gid & (T_SZ - 1);
    int b  = gid / (H_SZ * T_SZ);
    size_t row = (size_t)gid * T_SZ;
    int tid = threadIdx.x;
    const float scale = 0.125f;
    int qblk  = tq >> 5;
    int qbmin = (tq >> 7) << 2;
    int qbmax = qbmin + 3;

    float v[4];
    bool wlive[2];
    float mx = -3.4e38f;
#pragma unroll
    for (int i = 0; i < 2; i++) {
        int p  = tid + i * 256;
        int kb = p >> 4;
        bool blive = (kb <= qblk) && (sel[b * M_BLK + kb] || kb == qblk);
        wlive[i]   = (kb <= qbmax) && (sel[b * M_BLK + kb] || kb >= qbmin);
        float2 vv = make_float2(-1e9f, -1e9f);
        if (blive) vv = *reinterpret_cast<const float2*>(s + row + 2 * p);
        int e0 = 2 * p;
        v[2*i]   = (blive && e0     <= tq) ? vv.x * scale : -1e9f;
        v[2*i+1] = (blive && e0 + 1 <= tq) ? vv.y * scale : -1e9f;
        mx = fmaxf(mx, fmaxf(v[2*i], v[2*i+1]));
    }
    for (int o = 16; o > 0; o >>= 1) mx = fmaxf(mx, __shfl_xor_sync(0xffffffffu, mx, o));
    __shared__ float red[8];
    if ((tid & 31) == 0) red[tid >> 5] = mx;
    __syncthreads();
    float m = red[0];
    for (int i = 1; i < 8; i++) m = fmaxf(m, red[i]);
    __syncthreads();
    float sum = 0.f;
#pragma unroll
    for (int i = 0; i < 4; i++) { v[i] = expf(v[i] - m); sum += v[i]; }
    for (int o = 16; o > 0; o >>= 1) sum += __shfl_xor_sync(0xffffffffu, sum, o);
    if ((tid & 31) == 0) red[tid >> 5] = sum;
    __syncthreads();
    float tot = 0.f;
    for (int i = 0; i < 8; i++) tot += red[i];
    float inv = 1.f / tot;
    size_t prow = row >> 1;
#pragma unroll
    for (int i = 0; i < 2; i++) {
        if (!wlive[i]) continue;
        int p = tid + i * 256;
        u32 hh_, ll_;
        split2(v[2*i] * inv, v[2*i+1] * inv, hh_, ll_);
        ph[prow + p] = hh_; pl[prow + p] = ll_;
    }
}

__global__ __launch_bounds__(256) void silu_split_kernel(const float* __restrict__ f13,
                                                         u32* __restrict__ gh, u32* __restrict__ gl,
                                                         long n2)
{
    long idx = (long)blockIdx.x * blockDim.x + threadIdx.x;
    if (idx >= n2) return;
    const long F3OFF = (long)B_SZ * T_SZ * FF_SZ / 2;
    float2 a = reinterpret_cast<const float2*>(f13)[idx];
    float2 g = reinterpret_cast<const float2*>(f13)[F3OFF + idx];
    float y0 = a.x / (1.f + expf(-a.x)) * g.x;
    float y1 = a.y / (1.f + expf(-a.y)) * g.y;
    u32 h, l;
    split2(y0, y1, h, l);
    gh[idx] = h; gl[idx] = l;
}

// ---------------- host launchers ----------------
static const int SMEM_KN64 = NSTG * (2*128*LDA_S + 2*32*(64+8)) * 2;
static const int SMEM_NK64 = NSTG * (2*128*LDA_S + 2*64*LDA_S)  * 2;

static void gemm_kn_s(cudaStream_t st,
                      const u16* Ah, const u16* Al, const u16* Bh, const u16* Bl, float* C,
                      int M, int N, int K, int lda, int ldb, int ldc,
                      long sAb, long sBb, long sCb, long sAh, long sBh, long sCh,
                      int Hdim, int nb, int beta,
                      const int* sel = 0, int smode = 0, u16* Ch = 0, u16* Cl = 0)
{
    dim3 grid(N / 64, M / 128, nb);
    bf16_gemm_kernel<false><<<grid, 256, SMEM_KN64, st>>>(
        Ah, Al, Bh, Bl, C, K, lda, ldb, ldc, sAb, sBb, sCb, sAh, sBh, sCh, Hdim, beta,
        sel, smode, (u32*)Ch, (u32*)Cl);
}

static void gemm_nk(const u16* Ah, const u16* Al, const u16* Bh, const u16* Bl, float* C,
                    int M, int N, int K, int lda, int ldb, int ldc,
                    long sAb, long sBb, long sCb, long sAh, long sBh, long sCh,
                    int Hdim, int nb, int beta, const int* sel, int smode)
{
    dim3 grid(N / 64, M / 128, nb);
    bf16_gemm_kernel<true><<<grid, 256, SMEM_NK64>>>(
        Ah, Al, Bh, Bl, C, K, lda, ldb, ldc, sAb, sBb, sCb, sAh, sBh, sCh, Hdim, beta,
        sel, smode, (u32*)0, (u32*)0);
}

static void split_s(cudaStream_t st, const float* in, u16* hi, u16* lo, long n)
{
    long n4 = n / 4;
    split_kernel<<<(unsigned)((n4 + 255) / 256), 256, 0, st>>>(
        in, (uint2*)hi, (uint2*)lo, n4);
}

extern "C" void kernel_launch(void* const* d_in, const int* in_sizes, int n_in,
                              void* d_out, int out_size)
{
    const int*   ids        = (const int*)  d_in[0];
    const float* emb        = (const float*)d_in[1];
    const float* wq         = (const float*)d_in[2];
    const float* wk         = (const float*)d_in[3];
    const float* wv         = (const float*)d_in[4];
    const float* wo         = (const float*)d_in[5];
    const float* w1         = (const float*)d_in[6];
    const float* w2         = (const float*)d_in[7];
    const float* w3         = (const float*)d_in[8];
    const float* attn_norm  = (const float*)d_in[9];
    const float* ffn_norm   = (const float*)d_in[10];
    const float* final_norm = (const float*)d_in[11];
    const float* lm_head    = (const float*)d_in[12];
    float* out = (float*)d_out;

    static bool attrs_set = false;
    static cudaStream_t s1 = 0, s2 = 0;
    static cudaEvent_t evFork = 0, evW = 0, evEmb = 0, evSel = 0;
    if (!attrs_set) {
        cudaFuncSetAttribute(bf16_gemm_kernel<false>,
                             cudaFuncAttributeMaxDynamicSharedMemorySize, SMEM_KN64);
        cudaFuncSetAttribute(bf16_gemm_kernel<true>,
                             cudaFuncAttributeMaxDynamicSharedMemorySize, SMEM_NK64);
        cudaStreamCreateWithFlags(&s1, cudaStreamNonBlocking);
        cudaStreamCreateWithFlags(&s2, cudaStreamNonBlocking);
        cudaEventCreateWithFlags(&evFork, cudaEventDisableTiming);
        cudaEventCreateWithFlags(&evW,    cudaEventDisableTiming);
        cudaEventCreateWithFlags(&evEmb,  cudaEventDisableTiming);
        cudaEventCreateWithFlags(&evSel,  cudaEventDisableTiming);
        attrs_set = true;
    }

    float *x, *h, *qkv, *o, *sc, *f13, *G, *gk, *rho;
    int* sel;
    cudaGetSymbolAddress((void**)&x,   d_x);
    cudaGetSymbolAddress((void**)&h,   d_h);
    cudaGetSymbolAddress((void**)&qkv, d_qkv);
    cudaGetSymbolAddress((void**)&o,   d_o);
    cudaGetSymbolAddress((void**)&sc,  d_sc);
    cudaGetSymbolAddress((void**)&f13, d_f13);
    cudaGetSymbolAddress((void**)&G,   d_G);
    cudaGetSymbolAddress((void**)&gk,  d_gk);
    cudaGetSymbolAddress((void**)&rho, d_rho);
    cudaGetSymbolAddress((void**)&sel, d_sel);

    u16 *xh,*xl,*Gh,*Gl,*hh,*hl,*qkvh,*qkvl,*sch,*scl,*oh,*ol,*f1h,*f1l;
    u16 *wqkvh,*wqkvl,*woh,*wol,*w13h,*w13l,*w2h,*w2l,*lmh,*lml;
    cudaGetSymbolAddress((void**)&xh, d_xh);     cudaGetSymbolAddress((void**)&xl, d_xl);
    cudaGetSymbolAddress((void**)&Gh, d_Gh);     cudaGetSymbolAddress((void**)&Gl, d_Gl);
    cudaGetSymbolAddress((void**)&hh, d_hh);     cudaGetSymbolAddress((void**)&hl, d_hl);
    cudaGetSymbolAddress((void**)&qkvh, d_qkvh); cudaGetSymbolAddress((void**)&qkvl, d_qkvl);
    cudaGetSymbolAddress((void**)&sch, d_sch);   cudaGetSymbolAddress((void**)&scl, d_scl);
    cudaGetSymbolAddress((void**)&oh, d_oh);     cudaGetSymbolAddress((void**)&ol, d_ol);
    cudaGetSymbolAddress((void**)&f1h, d_f1h);   cudaGetSymbolAddress((void**)&f1l, d_f1l);
    cudaGetSymbolAddress((void**)&wqkvh, d_wqkvh); cudaGetSymbolAddress((void**)&wqkvl, d_wqkvl);
    cudaGetSymbolAddress((void**)&woh, d_woh);   cudaGetSymbolAddress((void**)&wol, d_wol);
    cudaGetSymbolAddress((void**)&w13h, d_w13h); cudaGetSymbolAddress((void**)&w13l, d_w13l);
    cudaGetSymbolAddress((void**)&w2h, d_w2h);   cudaGetSymbolAddress((void**)&w2l, d_w2l);
    cudaGetSymbolAddress((void**)&lmh, d_lmh);   cudaGetSymbolAddress((void**)&lml, d_lml);

    const int  BT = B_SZ * T_SZ;
    const long DD = (long)D_SZ * D_SZ;
    const long DF = (long)D_SZ * FF_SZ;
    const long QK = (long)BT * D_SZ;

    // ---- fork ----
    cudaEventRecord(evFork, 0);
    cudaStreamWaitEvent(s1, evFork, 0);
    cudaStreamWaitEvent(s2, evFork, 0);

    // s1: weight splits (QKV layer 0 first so evW can fire ASAP for consumers)
    for (int l = 0; l < L_SZ; l++) {
        split_s(s1, wq + l * DD, wqkvh + (3 * l + 0) * DD, wqkvl + (3 * l + 0) * DD, DD);
        split_s(s1, wk + l * DD, wqkvh + (3 * l + 1) * DD, wqkvl + (3 * l + 1) * DD, DD);
        split_s(s1, wv + l * DD, wqkvh + (3 * l + 2) * DD, wqkvl + (3 * l + 2) * DD, DD);
        split_s(s1, w1 + l * DF, w13h + (2 * l + 0) * DF, w13l + (2 * l + 0) * DF, DF);
        split_s(s1, w3 + l * DF, w13h + (2 * l + 1) * DF, w13l + (2 * l + 1) * DF, DF);
    }
    split_s(s1, wo, woh, wol, (long)L_SZ * DD);
    split_s(s1, w2, w2h, w2l, (long)L_SZ * DF);
    split_s(s1, lm_head, lmh, lml, (long)D_SZ * V_SZ);
    cudaEventRecord(evW, s1);

    // s2: Dirichlet table + G (no deps), then wait embed for G@x -> rho -> select
    dirichlet_kernel<<<T_SZ / 256, 256, 0, s2>>>(gk);
    buildG_kernel<<<(T_SZ * T_SZ) / 256, 256, 0, s2>>>(gk, G);
    split_s(s2, G, Gh, Gl, (long)T_SZ * T_SZ);

    // s0: embedding (+split)
    embed_split_kernel<<<(B_SZ * T_SZ * D_SZ / 2) / 256, 256>>>(
        ids, emb, x, (u32*)xh, (u32*)xl);
    cudaEventRecord(evEmb, 0);
    cudaStreamWaitEvent(s2, evEmb, 0);

    // s2: low-pass quality -> block selection
    gemm_kn_s(s2, Gh, Gl, xh, xl, h, T_SZ, D_SZ, T_SZ, T_SZ, D_SZ, D_SZ,
              0, (long)T_SZ * D_SZ, (long)T_SZ * D_SZ, 0, 0, 0, 1, B_SZ, 0);
    rho_kernel<<<BT, 256, 0, s2>>>(h, x, rho);
    select_blocks<<<1, 64, 0, s2>>>(rho, sel);
    cudaEventRecord(evSel, s2);

    // s0: layer-0 front (needs x + weights only)
    rmsnorm_split_kernel<<<BT, 256>>>(x, attn_norm, (u32*)hh, (u32*)hl);
    cudaStreamWaitEvent(0, evW, 0);

    // 3) transformer layers
    for (int l = 0; l < L_SZ; l++) {
        if (l > 0)
            rmsnorm_split_kernel<<<BT, 256>>>(x, attn_norm + (size_t)l * D_SZ,
                                              (u32*)hh, (u32*)hl);

        // fused QKV (z in {0,1,2})
        gemm_kn_s(0, hh, hl, wqkvh + 3 * l * DD, wqkvl + 3 * l * DD, qkv,
                  BT, D_SZ, D_SZ, D_SZ, D_SZ, D_SZ,
                  0, 0, 0, 0, DD, QK, 3, 3, 0, 0, 0,
                  (u16*)qkvh, (u16*)qkvl);

        rope_split_kernel<<<(B_SZ * T_SZ * H_SZ * 16) / 256, 256>>>(
            qkv, (u32*)qkvh, (u32*)qkvl);

        if (l == 0) cudaStreamWaitEvent(0, evSel, 0);

        gemm_nk(qkvh, qkvl, qkvh + QK, qkvl + QK, sc, T_SZ, T_SZ, DH_SZ,
                D_SZ, D_SZ, T_SZ,
                (long)T_SZ * D_SZ, (long)T_SZ * D_SZ, (long)H_SZ * T_SZ * T_SZ,
                DH_SZ, DH_SZ, (long)T_SZ * T_SZ, H_SZ, B_SZ * H_SZ, 0, sel, 1);

        masked_softmax_split_kernel<<<B_SZ * H_SZ * T_SZ, 256>>>(
            sc, sel, (u32*)sch, (u32*)scl);

        gemm_kn_s(0, sch, scl, qkvh + 2 * QK, qkvl + 2 * QK, o, T_SZ, DH_SZ, T_SZ,
                  T_SZ, D_SZ, D_SZ,
                  (long)H_SZ * T_SZ * T_SZ, (long)T_SZ * D_SZ, (long)T_SZ * D_SZ,
                  (long)T_SZ * T_SZ, DH_SZ, DH_SZ, H_SZ, B_SZ * H_SZ, 0, sel, 2, oh, ol);

        gemm_kn_s(0, oh, ol, woh + l * DD, wol + l * DD, x, BT, D_SZ, D_SZ, D_SZ, D_SZ, D_SZ,
                  0, 0, 0, 0, 0, 0, 1, 1, 1);

        // FFN: fused w1/w3 (z in {0,1})
        rmsnorm_split_kernel<<<BT, 256>>>(x, ffn_norm + (size_t)l * D_SZ, (u32*)hh, (u32*)hl);
        gemm_kn_s(0, hh, hl, w13h + 2 * l * DF, w13l + 2 * l * DF, f13,
                  BT, FF_SZ, D_SZ, D_SZ, FF_SZ, FF_SZ,
                  0, 0, 0, 0, DF, (long)BT * FF_SZ, 2, 2, 0);
        silu_split_kernel<<<(BT * FF_SZ / 2 + 255) / 256, 256>>>(
            f13, (u32*)f1h, (u32*)f1l, (long)BT * FF_SZ / 2);
        gemm_kn_s(0, f1h, f1l, w2h + l * DF, w2l + l * DF, x, BT, D_SZ, FF_SZ, FF_SZ, D_SZ, D_SZ,
                  0, 0, 0, 0, 0, 0, 1, 1, 1);
    }

    // 4) final norm + lm_head
    rmsnorm_split_kernel<<<BT, 256>>>(x, final_norm, (u32*)hh, (u32*)hl);
    gemm_kn_s(0, hh, hl, lmh, lml, out, BT, V_SZ, D_SZ, D_SZ, V_SZ, V_SZ,
              0, 0, 0, 0, 0, 0, 1, 1, 0);
}

// round 17
// speedup vs baseline: 1.1275x; 1.0017x over previous
#include <cuda_runtime.h>
#include <math.h>

typedef unsigned short u16;
typedef unsigned int   u32;

// ---------------- problem constants ----------------
#define B_SZ 2
#define T_SZ 1024
#define D_SZ 1024
#define H_SZ 16
#define DH_SZ 64
#define FF_SZ 4096
#define L_SZ 2
#define V_SZ 32000
#define M_BLK 32
#define BS_SZ 32
#define TOPK 8
#define KEEP 128
#define EPSF 1e-6f
#define PI_D 3.14159265358979323846

// ---------------- fp32 scratch ----------------
__device__ float d_x  [B_SZ*T_SZ*D_SZ];
__device__ float d_h  [B_SZ*T_SZ*D_SZ];
__device__ float d_qkv[3*B_SZ*T_SZ*D_SZ];            // contiguous q|k|v
__device__ float d_o  [B_SZ*T_SZ*D_SZ];
__device__ float d_sc [(size_t)B_SZ*H_SZ*T_SZ*T_SZ];
__device__ float d_f13[2*B_SZ*T_SZ*FF_SZ];           // contiguous f1|f3
__device__ float d_G  [T_SZ*T_SZ];
__device__ float d_gk [T_SZ];
__device__ float d_rho[B_SZ*T_SZ];
__device__ int   d_sel[B_SZ*M_BLK];

// ---------------- bf16 hi/lo planes ----------------
__device__ u16 d_xh  [B_SZ*T_SZ*D_SZ],   d_xl  [B_SZ*T_SZ*D_SZ];
__device__ u16 d_Gh  [T_SZ*T_SZ],        d_Gl  [T_SZ*T_SZ];
__device__ u16 d_hh  [B_SZ*T_SZ*D_SZ],   d_hl  [B_SZ*T_SZ*D_SZ];
__device__ u16 d_qkvh[3*B_SZ*T_SZ*D_SZ], d_qkvl[3*B_SZ*T_SZ*D_SZ];
__device__ u16 d_sch [(size_t)B_SZ*H_SZ*T_SZ*T_SZ], d_scl[(size_t)B_SZ*H_SZ*T_SZ*T_SZ];
__device__ u16 d_oh  [B_SZ*T_SZ*D_SZ],   d_ol  [B_SZ*T_SZ*D_SZ];
__device__ u16 d_f1h [B_SZ*T_SZ*FF_SZ],  d_f1l [B_SZ*T_SZ*FF_SZ];
// weights (natural [K][N] layout planes)
__device__ u16 d_wqkvh[L_SZ*3*D_SZ*D_SZ], d_wqkvl[L_SZ*3*D_SZ*D_SZ];
__device__ u16 d_woh [L_SZ*D_SZ*D_SZ],   d_wol [L_SZ*D_SZ*D_SZ];
__device__ u16 d_w13h[L_SZ*2*D_SZ*FF_SZ], d_w13l[L_SZ*2*D_SZ*FF_SZ];
__device__ u16 d_w2h [L_SZ*FF_SZ*D_SZ],  d_w2l [L_SZ*FF_SZ*D_SZ];
__device__ u16 d_lmh [(size_t)D_SZ*V_SZ], d_lml [(size_t)D_SZ*V_SZ];

// ---------------- split helpers ----------------
__device__ __forceinline__ void split2(float v0, float v1, u32 &hi, u32 &lo)
{
    asm("cvt.rn.bf16x2.f32 %0, %1, %2;" : "=r"(hi) : "f"(v1), "f"(v0));
    float h0 = __int_as_float(hi << 16);
    float h1 = __int_as_float(hi & 0xffff0000u);
    asm("cvt.rn.bf16x2.f32 %0, %1, %2;" : "=r"(lo) : "f"(v1 - h1), "f"(v0 - h0));
}

__global__ __launch_bounds__(256) void split_kernel(const float* __restrict__ in,
                                                    uint2* __restrict__ hi, uint2* __restrict__ lo,
                                                    long n4)
{
    long idx = (long)blockIdx.x * blockDim.x + threadIdx.x;
    if (idx >= n4) return;
    float4 v = reinterpret_cast<const float4*>(in)[idx];
    u32 h0, l0, h1, l1;
    split2(v.x, v.y, h0, l0);
    split2(v.z, v.w, h1, l1);
    hi[idx] = make_uint2(h0, h1);
    lo[idx] = make_uint2(l0, l1);
}

#define MMA_BF16(ACC, A, B0, B1)                                                 \
    asm volatile(                                                                \
        "mma.sync.aligned.m16n8k16.row.col.f32.bf16.bf16.f32 "                   \
        "{%0,%1,%2,%3}, {%4,%5,%6,%7}, {%8,%9}, {%0,%1,%2,%3};"                  \
        : "+f"(ACC[0]), "+f"(ACC[1]), "+f"(ACC[2]), "+f"(ACC[3])                 \
        : "r"(A[0]), "r"(A[1]), "r"(A[2]), "r"(A[3]), "r"(B0), "r"(B1))

#define LDSM4(R, ADDR)                                                           \
    asm volatile("ldmatrix.sync.aligned.m8n8.x4.shared.b16 {%0,%1,%2,%3},[%4];"  \
        : "=r"(R[0]), "=r"(R[1]), "=r"(R[2]), "=r"(R[3]) : "r"(ADDR))

#define LDSM4T(R0, R1, R2, R3, ADDR)                                             \
    asm volatile("ldmatrix.sync.aligned.m8n8.x4.trans.shared.b16 {%0,%1,%2,%3},[%4];" \
        : "=r"(R0), "=r"(R1), "=r"(R2), "=r"(R3) : "r"(ADDR))

// =====================================================================
// bf16 hi/lo 3-term GEMM, 3-stage cp.async pipeline, block-sparse modes.
// smode 0: dense. smode 1: scores (skip dead output tiles).
// smode 2: attn@V (iterate only live 32-wide K blocks).
// Optional Chp/Clp: epilogue also emits bf16 hi/lo planes (beta=0 only).
// BNK=true: B stored row-major [N][K].
// =====================================================================
#define LDA_S 40   // u16 stride (80B)
#define NSTG 3

template<bool BNK>
__global__ __launch_bounds__(256, 2)
void bf16_gemm_kernel(const u16* __restrict__ Ahi, const u16* __restrict__ Alo,
                      const u16* __restrict__ Bhi, const u16* __restrict__ Blo,
                      float* __restrict__ Cg,
                      int K, int lda, int ldb, int ldc,
                      long sAb, long sBb, long sCb, long sAh, long sBh, long sCh,
                      int Hdim, int beta,
                      const int* __restrict__ selp, int smode,
                      u32* __restrict__ Chp, u32* __restrict__ Clp)
{
    constexpr int BM = 128, BK = 32, BN = 64, WM = 4, WN = 2;
    constexpr int AM = 2, AN = 4;
    constexpr int LDB_S = BNK ? LDA_S : (BN + 8);
    constexpr int A_PL  = BM * LDA_S;
    constexpr int B_PL  = BNK ? (BN * LDA_S) : (BK * LDB_S);
    constexpr int STAGE = 2 * A_PL + 2 * B_PL;

    extern __shared__ u16 smu[];
    __shared__ int klist[129];
    __shared__ int kcnt;

    int z = blockIdx.z, zb = z / Hdim, zh = z % Hdim;
    const int tid = threadIdx.x, lane = tid & 31, w = tid >> 5;
    const int row0 = blockIdx.y * BM, col0 = blockIdx.x * BN;

    if (smode == 1) {
        int qbmin = row0 >> 5, qbmax = qbmin + 3;
        bool need = false;
#pragma unroll
        for (int i = 0; i < 2; i++) {
            int kb = (col0 >> 5) + i;
            if (kb <= qbmax && (selp[zb * M_BLK + kb] || kb >= qbmin)) need = true;
        }
        if (!need) return;
    }
    if (tid == 0) {
        int c = 0;
        if (smode == 2) {
            int qbmin = row0 >> 5, qbmax = qbmin + 3;
            for (int kb = 0; kb < K / 32; kb++)
                if (kb <= qbmax && (selp[zb * M_BLK + kb] || kb >= qbmin))
                    klist[c++] = kb * 32;
        } else {
            for (int t = 0; t < K / BK; t++) klist[c++] = t * BK;
        }
        kcnt = c;
    }
    __syncthreads();
    const int ntiles = kcnt;

    const u16* Ah = Ahi + zb * sAb + zh * sAh;
    const u16* Al = Alo + zb * sAb + zh * sAh;
    const u16* Bh = Bhi + zb * sBb + zh * sBh;
    const u16* Bl = Blo + zb * sBb + zh * sBh;
    float*     C  = Cg  + zb * sCb + zh * sCh;
    u32* Ch = Chp ? Chp + (zb * sCb + zh * sCh) / 2 : (u32*)0;
    u32* Cl = Clp ? Clp + (zb * sCb + zh * sCh) / 2 : (u32*)0;

    const int wm = w % WM, wn = w / WM;
    const int mW = wm * (BM / WM), nW = wn * (BN / WN);

    float acc[AM][AN][4];
#pragma unroll
    for (int i = 0; i < AM; i++)
#pragma unroll
        for (int j = 0; j < AN; j++)
#pragma unroll
            for (int r = 0; r < 4; r++) acc[i][j][r] = 0.f;

    auto cpa = [&](u16* dst, const u16* src) {
        u32 d = (u32)__cvta_generic_to_shared(dst);
        asm volatile("cp.async.cg.shared.global [%0],[%1],16;\n" :: "r"(d), "l"(src));
    };
    auto load_tile = [&](int s, int kt) {
        u16* base = smu + s * STAGE;
#pragma unroll
        for (int i = 0; i < 2; i++) {
            int ch = tid + i * 256;
            int r = ch >> 2, c = ch & 3;
            size_t go = (size_t)(row0 + r) * lda + kt + c * 8;
            cpa(base + r * LDA_S + c * 8,        Ah + go);
            cpa(base + A_PL + r * LDA_S + c * 8, Al + go);
        }
        u16* bb = base + 2 * A_PL;
        if (BNK) {
            int r = tid >> 2, c = tid & 3;
            size_t go = (size_t)(col0 + r) * ldb + kt + c * 8;
            cpa(bb + r * LDA_S + c * 8,        Bh + go);
            cpa(bb + B_PL + r * LDA_S + c * 8, Bl + go);
        } else {
            int r = tid >> 3, c = tid & 7;
            size_t go = (size_t)(kt + r) * ldb + col0 + c * 8;
            cpa(bb + r * LDB_S + c * 8,        Bh + go);
            cpa(bb + B_PL + r * LDB_S + c * 8, Bl + go);
        }
    };

    // 3-stage pipeline: up to 2 tiles in flight while computing one.
    load_tile(0, klist[0]);
    asm volatile("cp.async.commit_group;\n" ::: "memory");
    if (ntiles > 1) {
        load_tile(1, klist[1]);
        asm volatile("cp.async.commit_group;\n" ::: "memory");
    }

    for (int t = 0; t < ntiles; t++) {
        int s = t % NSTG;
        if (t + 1 < ntiles) {
            asm volatile("cp.async.wait_group 1;\n" ::: "memory");
        } else {
            asm volatile("cp.async.wait_group 0;\n" ::: "memory");
        }
        __syncthreads();
        if (t + 2 < ntiles) {
            load_tile((t + 2) % NSTG, klist[t + 2]);
            asm volatile("cp.async.commit_group;\n" ::: "memory");
        }

        const u16* sa = smu + s * STAGE;
        const u16* sb = sa + 2 * A_PL;
#pragma unroll
        for (int ks = 0; ks < 2; ks++) {
            u32 ah[AM][4], al[AM][4], bh[AN][2], bl[AN][2];
            int arow = ((lane >> 3) & 1) * 8 + (lane & 7);
            int acol = ks * 16 + (lane >> 4) * 8;
#pragma unroll
            for (int am = 0; am < AM; am++) {
                const u16* p = sa + (mW + am * 16 + arow) * LDA_S + acol;
                u32 addr = (u32)__cvta_generic_to_shared(p);
                LDSM4(ah[am], addr);
                LDSM4(al[am], addr + A_PL * 2);
            }
            if (BNK) {
                int brow = ((lane >> 4) & 1) * 8 + (lane & 7);
                int bcol = ks * 16 + ((lane >> 3) & 1) * 8;
#pragma unroll
                for (int a2 = 0; a2 < AN / 2; a2++) {
                    const u16* p = sb + (nW + a2 * 16 + brow) * LDA_S + bcol;
                    u32 addr = (u32)__cvta_generic_to_shared(p);
                    asm volatile("ldmatrix.sync.aligned.m8n8.x4.shared.b16 {%0,%1,%2,%3},[%4];"
                        : "=r"(bh[2*a2][0]), "=r"(bh[2*a2][1]),
                          "=r"(bh[2*a2+1][0]), "=r"(bh[2*a2+1][1]) : "r"(addr));
                    asm volatile("ldmatrix.sync.aligned.m8n8.x4.shared.b16 {%0,%1,%2,%3},[%4];"
                        : "=r"(bl[2*a2][0]), "=r"(bl[2*a2][1]),
                          "=r"(bl[2*a2+1][0]), "=r"(bl[2*a2+1][1]) : "r"(addr + B_PL * 2));
                }
            } else {
                int brow = ks * 16 + ((lane >> 3) & 1) * 8 + (lane & 7);
                int bcol = (lane >> 4) * 8;
#pragma unroll
                for (int a2 = 0; a2 < AN / 2; a2++) {
                    const u16* p = sb + brow * LDB_S + nW + a2 * 16 + bcol;
                    u32 addr = (u32)__cvta_generic_to_shared(p);
                    LDSM4T(bh[2*a2][0], bh[2*a2][1], bh[2*a2+1][0], bh[2*a2+1][1], addr);
                    LDSM4T(bl[2*a2][0], bl[2*a2][1], bl[2*a2+1][0], bl[2*a2+1][1],
                           addr + B_PL * 2);
                }
            }
#pragma unroll
            for (int am = 0; am < AM; am++)
#pragma unroll
                for (int an = 0; an < AN; an++) {
                    MMA_BF16(acc[am][an], ah[am], bh[an][0], bh[an][1]);
                    MMA_BF16(acc[am][an], ah[am], bl[an][0], bl[an][1]);
                    MMA_BF16(acc[am][an], al[am], bh[an][0], bh[an][1]);
                }
        }
        __syncthreads();
    }

#pragma unroll
    for (int am = 0; am < AM; am++)
#pragma unroll
        for (int an = 0; an < AN; an++) {
            int r = row0 + mW + am * 16 + (lane >> 2);
            int c = col0 + nW + an * 8 + (lane & 3) * 2;
            size_t i0 = (size_t)r * ldc + c;
            size_t i1 = (size_t)(r + 8) * ldc + c;
            float2 v0 = make_float2(acc[am][an][0], acc[am][an][1]);
            float2 v1 = make_float2(acc[am][an][2], acc[am][an][3]);
            if (beta) {
                float2 p0 = *reinterpret_cast<const float2*>(C + i0);
                float2 p1 = *reinterpret_cast<const float2*>(C + i1);
                v0.x += p0.x; v0.y += p0.y; v1.x += p1.x; v1.y += p1.y;
            }
            *reinterpret_cast<float2*>(C + i0) = v0;
            *reinterpret_cast<float2*>(C + i1) = v1;
            if (Ch) {
                u32 hh_, ll_;
                split2(v0.x, v0.y, hh_, ll_);
                Ch[i0 >> 1] = hh_; Cl[i0 >> 1] = ll_;
                split2(v1.x, v1.y, hh_, ll_);
                Ch[i1 >> 1] = hh_; Cl[i1 >> 1] = ll_;
            }
        }
}

// ---------------- elementwise kernels ----------------
__global__ void embed_split_kernel(const int* __restrict__ ids, const float* __restrict__ emb,
                                   float* __restrict__ x, u32* __restrict__ xh, u32* __restrict__ xl)
{
    int idx = blockIdx.x * blockDim.x + threadIdx.x;   // B*T*D/2
    int d2 = idx & 511;
    int bt = idx >> 9;
    float2 v = *reinterpret_cast<const float2*>(emb + (size_t)ids[bt] * D_SZ + d2 * 2);
    *reinterpret_cast<float2*>(x + (size_t)bt * D_SZ + d2 * 2) = v;
    u32 h, l;
    split2(v.x, v.y, h, l);
    xh[idx] = h; xl[idx] = l;
}

__global__ void dirichlet_kernel(float* __restrict__ g)
{
    int d = blockIdx.x * blockDim.x + threadIdx.x;
    if (d >= T_SZ) return;
    double s = 0.0;
    for (int k = 1; k < KEEP; k++)
        s += cos(2.0 * PI_D * (double)k * (double)d / (double)T_SZ);
    g[d] = (float)((1.0 + 2.0 * s) / (double)T_SZ);
}

__global__ void buildG_kernel(const float* __restrict__ g, float* __restrict__ G)
{
    int i = blockIdx.x * blockDim.x + threadIdx.x;
    int t = i >> 10, s = i & (T_SZ - 1);
    G[i] = g[(t - s) & (T_SZ - 1)];
}

__global__ __launch_bounds__(256) void rho_kernel(const float* __restrict__ hlp,
                                                  const float* __restrict__ x,
                                                  float* __restrict__ rho)
{
    size_t row = (size_t)blockIdx.x * D_SZ;
    int tid = threadIdx.x;
    float s1 = 0.f, s2 = 0.f;
#pragma unroll
    for (int i = 0; i < 4; i++) {
        float a = hlp[row + tid + i * 256];
        float b = x  [row + tid + i * 256];
        s1 += a * a; s2 += b * b;
    }
    for (int o = 16; o > 0; o >>= 1) {
        s1 += __shfl_xor_sync(0xffffffffu, s1, o);
        s2 += __shfl_xor_sync(0xffffffffu, s2, o);
    }
    __shared__ float r1[8], r2[8];
    if ((tid & 31) == 0) { r1[tid >> 5] = s1; r2[tid >> 5] = s2; }
    __syncthreads();
    if (tid == 0) {
        float t1 = 0.f, t2 = 0.f;
        for (int i = 0; i < 8; i++) { t1 += r1[i]; t2 += r2[i]; }
        rho[blockIdx.x] = t1 / (t2 + EPSF);
    }
}

__global__ void select_blocks(const float* __restrict__ rho, int* __restrict__ sel)
{
    __shared__ float bq[B_SZ][M_BLK];
    int tid = threadIdx.x;
    if (tid < B_SZ * M_BLK) {
        int b = tid >> 5, m = tid & 31;
        float s = 0.f;
        for (int i = 0; i < BS_SZ; i++) s += rho[b * T_SZ + m * BS_SZ + i];
        bq[b][m] = s * (1.f / BS_SZ);
        sel[tid] = 0;
    }
    __syncthreads();
    if (tid < B_SZ) {
        int b = tid;
        bool picked[M_BLK];
        for (int m = 0; m < M_BLK; m++) picked[m] = false;
        for (int it = 0; it < TOPK; it++) {
            int best = -1; float bv = -3.4e38f;
            for (int m = 0; m < M_BLK; m++)
                if (!picked[m] && bq[b][m] > bv) { bv = bq[b][m]; best = m; }
            picked[best] = true;
            sel[b * M_BLK + best] = 1;
        }
    }
}

__global__ __launch_bounds__(256) void rmsnorm_split_kernel(
    const float* __restrict__ x, const float* __restrict__ w,
    u32* __restrict__ yh, u32* __restrict__ yl)
{
    size_t row = (size_t)blockIdx.x * D_SZ;
    int tid = threadIdx.x;
    float4 v = reinterpret_cast<const float4*>(x + row)[tid];
    float s = v.x * v.x + v.y * v.y + v.z * v.z + v.w * v.w;
    for (int o = 16; o > 0; o >>= 1) s += __shfl_xor_sync(0xffffffffu, s, o);
    __shared__ float red[8];
    if ((tid & 31) == 0) red[tid >> 5] = s;
    __syncthreads();
    float tot = 0.f;
    for (int i = 0; i < 8; i++) tot += red[i];
    float r = rsqrtf(tot * (1.f / D_SZ) + EPSF);
    float4 wv = reinterpret_cast<const float4*>(w)[tid];
    u32 h0, l0, h1, l1;
    split2(v.x * r * wv.x, v.y * r * wv.y, h0, l0);
    split2(v.z * r * wv.z, v.w * r * wv.w, h1, l1);
    size_t c = row / 2 + tid * 2;
    yh[c] = h0; yh[c + 1] = h1;
    yl[c] = l0; yl[c + 1] = l1;
}

__global__ void rope_split_kernel(const float* __restrict__ qkv,
                                  u32* __restrict__ qkvh, u32* __restrict__ qkvl)
{
    const int QK = B_SZ * T_SZ * D_SZ;
    int idx = blockIdx.x * blockDim.x + threadIdx.x;   // B*T*H*16
    int j2 = idx & 15;
    int h  = (idx >> 4) & (H_SZ - 1);
    int t  = (idx >> 8) & (T_SZ - 1);
    int b  = idx >> 18;
    int e0 = 2 * j2;
    float inv0 = (float)(1.0 / pow(10000.0, (double)(2 * e0)     / (double)DH_SZ));
    float inv1 = (float)(1.0 / pow(10000.0, (double)(2 * (e0+1)) / (double)DH_SZ));
    float c0 = cosf(t * inv0), s0 = sinf(t * inv0);
    float c1 = cosf(t * inv1), s1 = sinf(t * inv1);
    size_t base = ((size_t)(b * T_SZ + t)) * D_SZ + h * DH_SZ + e0;
    float2 qa = *reinterpret_cast<const float2*>(qkv + base);
    float2 qb = *reinterpret_cast<const float2*>(qkv + base + 32);
    float2 ka = *reinterpret_cast<const float2*>(qkv + QK + base);
    float2 kb = *reinterpret_cast<const float2*>(qkv + QK + base + 32);
    float q0 = qa.x * c0 - qb.x * s0, q1 = qa.y * c1 - qb.y * s1;
    float q2 = qb.x * c0 + qa.x * s0, q3 = qb.y * c1 + qa.y * s1;
    float k0 = ka.x * c0 - kb.x * s0, k1 = ka.y * c1 - kb.y * s1;
    float k2 = kb.x * c0 + ka.x * s0, k3 = kb.y * c1 + ka.y * s1;
    size_t p0 = base >> 1, p1 = (base + 32) >> 1;
    const size_t QK2 = QK / 2;
    u32 hh_, ll_;
    split2(q0, q1, hh_, ll_); qkvh[p0] = hh_;       qkvl[p0] = ll_;
    split2(q2, q3, hh_, ll_); qkvh[p1] = hh_;       qkvl[p1] = ll_;
    split2(k0, k1, hh_, ll_); qkvh[QK2 + p0] = hh_; qkvl[QK2 + p0] = ll_;
    split2(k2, k3, hh_, ll_); qkvh[QK2 + p1] = hh_; qkvl[QK2 + p1] = ll_;
}

__global__ __launch_bounds__(256) void masked_softmax_split_kernel(
    const float* __restrict__ s, const int* __restrict__ sel,
    u32* __restrict__ ph, u32* __restrict__ pl)
{
    int gid = blockIdx.x;
    int tq = gid & (T_SZ - 1);
    int b  = gid / (H_SZ * T_SZ);
    size_t row = (size_t)gid * T_SZ;
    int tid = threadIdx.x;
    const float scale = 0.125f;
    int qblk  = tq >> 5;
    int qbmin = (tq >> 7) << 2;
    int qbmax = qbmin + 3;

    float v[4];
    bool wlive[2];
    float mx = -3.4e38f;
#pragma unroll
    for (int i = 0; i < 2; i++) {
        int p  = tid + i * 256;
        int kb = p >> 4;
        bool blive = (kb <= qblk) && (sel[b * M_BLK + kb] || kb == qblk);
        wlive[i]   = (kb <= qbmax) && (sel[b * M_BLK + kb] || kb >= qbmin);
        float2 vv = make_float2(-1e9f, -1e9f);
        if (blive) vv = *reinterpret_cast<const float2*>(s + row + 2 * p);
        int e0 = 2 * p;
        v[2*i]   = (blive && e0     <= tq) ? vv.x * scale : -1e9f;
        v[2*i+1] = (blive && e0 + 1 <= tq) ? vv.y * scale : -1e9f;
        mx = fmaxf(mx, fmaxf(v[2*i], v[2*i+1]));
    }
    for (int o = 16; o > 0; o >>= 1) mx = fmaxf(mx, __shfl_xor_sync(0xffffffffu, mx, o));
    __shared__ float red[8];
    if ((tid & 31) == 0) red[tid >> 5] = mx;
    __syncthreads();
    float m = red[0];
    for (int i = 1; i < 8; i++) m = fmaxf(m, red[i]);
    __syncthreads();
    float sum = 0.f;
#pragma unroll
    for (int i = 0; i < 4; i++) { v[i] = expf(v[i] - m); sum += v[i]; }
    for (int o = 16; o > 0; o >>= 1) sum += __shfl_xor_sync(0xffffffffu, sum, o);
    if ((tid & 31) == 0) red[tid >> 5] = sum;
    __syncthreads();
    float tot = 0.f;
    for (int i = 0; i < 8; i++) tot += red[i];
    float inv = 1.f / tot;
    size_t prow = row >> 1;
#pragma unroll
    for (int i = 0; i < 2; i++) {
        if (!wlive[i]) continue;
        int p = tid + i * 256;
        u32 hh_, ll_;
        split2(v[2*i] * inv, v[2*i+1] * inv, hh_, ll_);
        ph[prow + p] = hh_; pl[prow + p] = ll_;
    }
}

__global__ __launch_bounds__(256) void silu_split_kernel(const float* __restrict__ f13,
                                                         u32* __restrict__ gh, u32* __restrict__ gl,
                                                         long n2)
{
    long idx = (long)blockIdx.x * blockDim.x + threadIdx.x;
    if (idx >= n2) return;
    const long F3OFF = (long)B_SZ * T_SZ * FF_SZ / 2;
    float2 a = reinterpret_cast<const float2*>(f13)[idx];
    float2 g = reinterpret_cast<const float2*>(f13)[F3OFF + idx];
    float y0 = a.x / (1.f + expf(-a.x)) * g.x;
    float y1 = a.y / (1.f + expf(-a.y)) * g.y;
    u32 h, l;
    split2(y0, y1, h, l);
    gh[idx] = h; gl[idx] = l;
}

// ---------------- host launchers ----------------
static const int SMEM_KN64 = NSTG * (2*128*LDA_S + 2*32*(64+8)) * 2;
static const int SMEM_NK64 = NSTG * (2*128*LDA_S + 2*64*LDA_S)  * 2;

static void gemm_kn_s(cudaStream_t st,
                      const u16* Ah, const u16* Al, const u16* Bh, const u16* Bl, float* C,
                      int M, int N, int K, int lda, int ldb, int ldc,
                      long sAb, long sBb, long sCb, long sAh, long sBh, long sCh,
                      int Hdim, int nb, int beta,
                      const int* sel = 0, int smode = 0, u16* Ch = 0, u16* Cl = 0)
{
    dim3 grid(N / 64, M / 128, nb);
    bf16_gemm_kernel<false><<<grid, 256, SMEM_KN64, st>>>(
        Ah, Al, Bh, Bl, C, K, lda, ldb, ldc, sAb, sBb, sCb, sAh, sBh, sCh, Hdim, beta,
        sel, smode, (u32*)Ch, (u32*)Cl);
}

static void gemm_nk(const u16* Ah, const u16* Al, const u16* Bh, const u16* Bl, float* C,
                    int M, int N, int K, int lda, int ldb, int ldc,
                    long sAb, long sBb, long sCb, long sAh, long sBh, long sCh,
                    int Hdim, int nb, int beta, const int* sel, int smode)
{
    dim3 grid(N / 64, M / 128, nb);
    bf16_gemm_kernel<true><<<grid, 256, SMEM_NK64>>>(
        Ah, Al, Bh, Bl, C, K, lda, ldb, ldc, sAb, sBb, sCb, sAh, sBh, sCh, Hdim, beta,
        sel, smode, (u32*)0, (u32*)0);
}

static void split_s(cudaStream_t st, const float* in, u16* hi, u16* lo, long n)
{
    long n4 = n / 4;
    split_kernel<<<(unsigned)((n4 + 255) / 256), 256, 0, st>>>(
        in, (uint2*)hi, (uint2*)lo, n4);
}

extern "C" void kernel_launch(void* const* d_in, const int* in_sizes, int n_in,
                              void* d_out, int out_size)
{
    const int*   ids        = (const int*)  d_in[0];
    const float* emb        = (const float*)d_in[1];
    const float* wq         = (const float*)d_in[2];
    const float* wk         = (const float*)d_in[3];
    const float* wv         = (const float*)d_in[4];
    const float* wo         = (const float*)d_in[5];
    const float* w1         = (const float*)d_in[6];
    const float* w2         = (const float*)d_in[7];
    const float* w3         = (const float*)d_in[8];
    const float* attn_norm  = (const float*)d_in[9];
    const float* ffn_norm   = (const float*)d_in[10];
    const float* final_norm = (const float*)d_in[11];
    const float* lm_head    = (const float*)d_in[12];
    float* out = (float*)d_out;

    static bool attrs_set = false;
    static cudaStream_t s1 = 0, s2 = 0;
    static cudaEvent_t evFork = 0, evW0 = 0, evW1 = 0, evWlm = 0, evEmb = 0, evSel = 0;
    if (!attrs_set) {
        cudaFuncSetAttribute(bf16_gemm_kernel<false>,
                             cudaFuncAttributeMaxDynamicSharedMemorySize, SMEM_KN64);
        cudaFuncSetAttribute(bf16_gemm_kernel<true>,
                             cudaFuncAttributeMaxDynamicSharedMemorySize, SMEM_NK64);
        cudaStreamCreateWithFlags(&s1, cudaStreamNonBlocking);
        cudaStreamCreateWithFlags(&s2, cudaStreamNonBlocking);
        cudaEventCreateWithFlags(&evFork, cudaEventDisableTiming);
        cudaEventCreateWithFlags(&evW0,   cudaEventDisableTiming);
        cudaEventCreateWithFlags(&evW1,   cudaEventDisableTiming);
        cudaEventCreateWithFlags(&evWlm,  cudaEventDisableTiming);
        cudaEventCreateWithFlags(&evEmb,  cudaEventDisableTiming);
        cudaEventCreateWithFlags(&evSel,  cudaEventDisableTiming);
        attrs_set = true;
    }

    float *x, *h, *qkv, *o, *sc, *f13, *G, *gk, *rho;
    int* sel;
    cudaGetSymbolAddress((void**)&x,   d_x);
    cudaGetSymbolAddress((void**)&h,   d_h);
    cudaGetSymbolAddress((void**)&qkv, d_qkv);
    cudaGetSymbolAddress((void**)&o,   d_o);
    cudaGetSymbolAddress((void**)&sc,  d_sc);
    cudaGetSymbolAddress((void**)&f13, d_f13);
    cudaGetSymbolAddress((void**)&G,   d_G);
    cudaGetSymbolAddress((void**)&gk,  d_gk);
    cudaGetSymbolAddress((void**)&rho, d_rho);
    cudaGetSymbolAddress((void**)&sel, d_sel);

    u16 *xh,*xl,*Gh,*Gl,*hh,*hl,*qkvh,*qkvl,*sch,*scl,*oh,*ol,*f1h,*f1l;
    u16 *wqkvh,*wqkvl,*woh,*wol,*w13h,*w13l,*w2h,*w2l,*lmh,*lml;
    cudaGetSymbolAddress((void**)&xh, d_xh);     cudaGetSymbolAddress((void**)&xl, d_xl);
    cudaGetSymbolAddress((void**)&Gh, d_Gh);     cudaGetSymbolAddress((void**)&Gl, d_Gl);
    cudaGetSymbolAddress((void**)&hh, d_hh);     cudaGetSymbolAddress((void**)&hl, d_hl);
    cudaGetSymbolAddress((void**)&qkvh, d_qkvh); cudaGetSymbolAddress((void**)&qkvl, d_qkvl);
    cudaGetSymbolAddress((void**)&sch, d_sch);   cudaGetSymbolAddress((void**)&scl, d_scl);
    cudaGetSymbolAddress((void**)&oh, d_oh);     cudaGetSymbolAddress((void**)&ol, d_ol);
    cudaGetSymbolAddress((void**)&f1h, d_f1h);   cudaGetSymbolAddress((void**)&f1l, d_f1l);
    cudaGetSymbolAddress((void**)&wqkvh, d_wqkvh); cudaGetSymbolAddress((void**)&wqkvl, d_wqkvl);
    cudaGetSymbolAddress((void**)&woh, d_woh);   cudaGetSymbolAddress((void**)&wol, d_wol);
    cudaGetSymbolAddress((void**)&w13h, d_w13h); cudaGetSymbolAddress((void**)&w13l, d_w13l);
    cudaGetSymbolAddress((void**)&w2h, d_w2h);   cudaGetSymbolAddress((void**)&w2l, d_w2l);
    cudaGetSymbolAddress((void**)&lmh, d_lmh);   cudaGetSymbolAddress((void**)&lml, d_lml);

    const int  BT = B_SZ * T_SZ;
    const long DD = (long)D_SZ * D_SZ;
    const long DF = (long)D_SZ * FF_SZ;
    const long QK = (long)BT * D_SZ;

    // ---- fork ----
    cudaEventRecord(evFork, 0);
    cudaStreamWaitEvent(s1, evFork, 0);
    cudaStreamWaitEvent(s2, evFork, 0);

    // s1 group 1: layer-0 QKV weights only -> evW0 (gates QKV_0)
    split_s(s1, wq, wqkvh + 0 * DD, wqkvl + 0 * DD, DD);
    split_s(s1, wk, wqkvh + 1 * DD, wqkvl + 1 * DD, DD);
    split_s(s1, wv, wqkvh + 2 * DD, wqkvl + 2 * DD, DD);
    cudaEventRecord(evW0, s1);

    // s1 group 2: all remaining layer weights -> evW1
    split_s(s1, w1, w13h + 0 * DF, w13l + 0 * DF, DF);
    split_s(s1, w3, w13h + 1 * DF, w13l + 1 * DF, DF);
    split_s(s1, wo, woh, wol, (long)L_SZ * DD);
    split_s(s1, w2, w2h, w2l, (long)L_SZ * DF);
    for (int l = 1; l < L_SZ; l++) {
        split_s(s1, wq + l * DD, wqkvh + (3 * l + 0) * DD, wqkvl + (3 * l + 0) * DD, DD);
        split_s(s1, wk + l * DD, wqkvh + (3 * l + 1) * DD, wqkvl + (3 * l + 1) * DD, DD);
        split_s(s1, wv + l * DD, wqkvh + (3 * l + 2) * DD, wqkvl + (3 * l + 2) * DD, DD);
        split_s(s1, w1 + l * DF, w13h + (2 * l + 0) * DF, w13l + (2 * l + 0) * DF, DF);
        split_s(s1, w3 + l * DF, w13h + (2 * l + 1) * DF, w13l + (2 * l + 1) * DF, DF);
    }
    cudaEventRecord(evW1, s1);

    // s1 group 3: lm_head (consumed only by the final GEMM) -> evWlm
    split_s(s1, lm_head, lmh, lml, (long)D_SZ * V_SZ);
    cudaEventRecord(evWlm, s1);

    // s2: Dirichlet table + G (no deps), then wait embed for G@x -> rho -> select
    dirichlet_kernel<<<T_SZ / 256, 256, 0, s2>>>(gk);
    buildG_kernel<<<(T_SZ * T_SZ) / 256, 256, 0, s2>>>(gk, G);
    split_s(s2, G, Gh, Gl, (long)T_SZ * T_SZ);

    // s0: embedding (+split)
    embed_split_kernel<<<(B_SZ * T_SZ * D_SZ / 2) / 256, 256>>>(
        ids, emb, x, (u32*)xh, (u32*)xl);
    cudaEventRecord(evEmb, 0);
    cudaStreamWaitEvent(s2, evEmb, 0);

    // s2: low-pass quality -> block selection
    gemm_kn_s(s2, Gh, Gl, xh, xl, h, T_SZ, D_SZ, T_SZ, T_SZ, D_SZ, D_SZ,
              0, (long)T_SZ * D_SZ, (long)T_SZ * D_SZ, 0, 0, 0, 1, B_SZ, 0);
    rho_kernel<<<BT, 256, 0, s2>>>(h, x, rho);
    select_blocks<<<1, 64, 0, s2>>>(rho, sel);
    cudaEventRecord(evSel, s2);

    // s0: layer-0 front (needs x + QKV_0 weights only)
    rmsnorm_split_kernel<<<BT, 256>>>(x, attn_norm, (u32*)hh, (u32*)hl);
    cudaStreamWaitEvent(0, evW0, 0);

    // 3) transformer layers
    for (int l = 0; l < L_SZ; l++) {
        if (l > 0)
            rmsnorm_split_kernel<<<BT, 256>>>(x, attn_norm + (size_t)l * D_SZ,
                                              (u32*)hh, (u32*)hl);

        // fused QKV (z in {0,1,2})
        gemm_kn_s(0, hh, hl, wqkvh + 3 * l * DD, wqkvl + 3 * l * DD, qkv,
                  BT, D_SZ, D_SZ, D_SZ, D_SZ, D_SZ,
                  0, 0, 0, 0, DD, QK, 3, 3, 0, 0, 0,
                  (u16*)qkvh, (u16*)qkvl);

        rope_split_kernel<<<(B_SZ * T_SZ * H_SZ * 16) / 256, 256>>>(
            qkv, (u32*)qkvh, (u32*)qkvl);

        if (l == 0) cudaStreamWaitEvent(0, evSel, 0);

        gemm_nk(qkvh, qkvl, qkvh + QK, qkvl + QK, sc, T_SZ, T_SZ, DH_SZ,
                D_SZ, D_SZ, T_SZ,
                (long)T_SZ * D_SZ, (long)T_SZ * D_SZ, (long)H_SZ * T_SZ * T_SZ,
                DH_SZ, DH_SZ, (long)T_SZ * T_SZ, H_SZ, B_SZ * H_SZ, 0, sel, 1);

        masked_softmax_split_kernel<<<B_SZ * H_SZ * T_SZ, 256>>>(
            sc, sel, (u32*)sch, (u32*)scl);

        gemm_kn_s(0, sch, scl, qkvh + 2 * QK, qkvl + 2 * QK, o, T_SZ, DH_SZ, T_SZ,
                  T_SZ, D_SZ, D_SZ,
                  (long)H_SZ * T_SZ * T_SZ, (long)T_SZ * D_SZ, (long)T_SZ * D_SZ,
                  (long)T_SZ * T_SZ, DH_SZ, DH_SZ, H_SZ, B_SZ * H_SZ, 0, sel, 2, oh, ol);

        if (l == 0) cudaStreamWaitEvent(0, evW1, 0);

        gemm_kn_s(0, oh, ol, woh + l * DD, wol + l * DD, x, BT, D_SZ, D_SZ, D_SZ, D_SZ, D_SZ,
                  0, 0, 0, 0, 0, 0, 1, 1, 1);

        // FFN: fused w1/w3 (z in {0,1})
        rmsnorm_split_kernel<<<BT, 256>>>(x, ffn_norm + (size_t)l * D_SZ, (u32*)hh, (u32*)hl);
        gemm_kn_s(0, hh, hl, w13h + 2 * l * DF, w13l + 2 * l * DF, f13,
                  BT, FF_SZ, D_SZ, D_SZ, FF_SZ, FF_SZ,
                  0, 0, 0, 0, DF, (long)BT * FF_SZ, 2, 2, 0);
        silu_split_kernel<<<(BT * FF_SZ / 2 + 255) / 256, 256>>>(
            f13, (u32*)f1h, (u32*)f1l, (long)BT * FF_SZ / 2);
        gemm_kn_s(0, f1h, f1l, w2h + l * DF, w2l + l * DF, x, BT, D_SZ, FF_SZ, FF_SZ, D_SZ, D_SZ,
                  0, 0, 0, 0, 0, 0, 1, 1, 1);
    }

    // 4) final norm + lm_head
    rmsnorm_split_kernel<<<BT, 256>>>(x, final_norm, (u32*)hh, (u32*)hl);
    cudaStreamWaitEvent(0, evWlm, 0);
    gemm_kn_s(0, hh, hl, lmh, lml, out, BT, V_SZ, D_SZ, D_SZ, V_SZ, V_SZ,
              0, 0, 0, 0, 0, 0, 1, 1, 0);
}